// round 12
// baseline (speedup 1.0000x reference)
#include <cuda_runtime.h>
#include <math.h>
#include <stdint.h>

// ---------------- problem constants ----------------
constexpr int NN   = 50000;
constexpr int EE   = 800000;
constexpr int DIM  = 128;
constexpr int NH   = 8;
constexpr int HID  = 512;

// ---------------- scratch ----------------
__device__ float g_xin  [(size_t)NN*DIM];
__device__ float g_h    [(size_t)NN*DIM];
__device__ float g_qkvs [(size_t)NN*4*DIM];   // q[0:128) k[128:256) v[256:384) skip[384:512)
__device__ float g_denom[(size_t)NN*NH];
__device__ float g_agg  [(size_t)NN*DIM];     // UNNORMALIZED sum of pe*(v+e)
__device__ float g_xattn[(size_t)NN*DIM];
__device__ float g_h2   [(size_t)NN*DIM];
__device__ float g_ffn1 [(size_t)NN*HID];
__device__ float g_xn   [(size_t)NN*DIM];
__device__ float g_P12  [(size_t)NN*256];     // xn @ [Wsrc | Wdst]
__device__ float g_W4   [(size_t)DIM*512];
__device__ float g_Wp   [(size_t)DIM*256];    // packed [euW[0:128] | euW[128:256]]
__device__ float g_b4   [512];
__device__ int   g_deg  [NN];

// ---------------- helpers ----------------
__device__ __forceinline__ float warp_sum(float v) {
#pragma unroll
    for (int o = 16; o > 0; o >>= 1) v += __shfl_xor_sync(0xffffffffu, v, o);
    return v;
}
__device__ __forceinline__ void mma_tf32(float* c,
                                         uint32_t a0, uint32_t a1, uint32_t a2, uint32_t a3,
                                         uint32_t b0, uint32_t b1) {
    asm volatile("mma.sync.aligned.m16n8k8.row.col.f32.tf32.tf32.f32 "
                 "{%0,%1,%2,%3}, {%4,%5,%6,%7}, {%8,%9}, {%0,%1,%2,%3};"
                 : "+f"(c[0]), "+f"(c[1]), "+f"(c[2]), "+f"(c[3])
                 : "r"(a0), "r"(a1), "r"(a2), "r"(a3), "r"(b0), "r"(b1));
}
__device__ __forceinline__ float gelu_erf(float v) {
    return 0.5f * v * (1.0f + erff(v * 0.70710678118654752f));
}
__device__ __forceinline__ void cp16(uint32_t d, const float* g) {
    asm volatile("cp.async.cg.shared.global [%0], [%1], 16;" :: "r"(d), "l"(g) : "memory");
}
__device__ __forceinline__ void cp_commit() {
    asm volatile("cp.async.commit_group;" ::: "memory");
}
template<int N> __device__ __forceinline__ void cp_wait() {
    asm volatile("cp.async.wait_group %0;" :: "n"(N) : "memory");
}

// smem tile geometry
constexpr int ALD = 36;
constexpr int BLD = 136;
constexpr int AOFF = 128*ALD;
constexpr int BOFF = 32*BLD;
constexpr int TILE_SMEM_U32 = 2*AOFF + 2*BOFF;   // 17920 u32 = 71680 B
constexpr int MMA_SMEM = TILE_SMEM_U32 * 4;

// ---------------- init / degree / pack ----------------
__global__ void k_init() {
    int i  = blockIdx.x * blockDim.x + threadIdx.x;
    int st = gridDim.x * blockDim.x;
    for (int j = i; j < NN*DIM; j += st) g_agg[j] = 0.0f;
    for (int j = i; j < NN*NH;  j += st) g_denom[j] = 0.0f;
    for (int j = i; j < NN;     j += st) g_deg[j] = 0;
}
__global__ void k_deg(const int* __restrict__ src) {
    int i = blockIdx.x * blockDim.x + threadIdx.x;
    if (i < EE) atomicAdd(&g_deg[src[i]], 1);
}
__global__ void k_pack(const float* __restrict__ Wq, const float* __restrict__ Wk,
                       const float* __restrict__ Wv, const float* __restrict__ Ws,
                       const float* __restrict__ bq, const float* __restrict__ bk,
                       const float* __restrict__ bv, const float* __restrict__ bs,
                       const float* __restrict__ euW) {
    int i = blockIdx.x * blockDim.x + threadIdx.x;
    if (i < DIM*DIM) {
        int r = i >> 7, c = i & 127;
        g_W4[(size_t)r*512 +       c] = Wq[i];
        g_W4[(size_t)r*512 + 128 + c] = Wk[i];
        g_W4[(size_t)r*512 + 256 + c] = Wv[i];
        g_W4[(size_t)r*512 + 384 + c] = Ws[i];
        g_Wp[(size_t)r*256 +       c] = euW[(size_t)r*128 + c];
        g_Wp[(size_t)r*256 + 128 + c] = euW[(size_t)(128 + r)*128 + c];
    }
    if (i < 128) {
        g_b4[i] = bq[i]; g_b4[128+i] = bk[i]; g_b4[256+i] = bv[i]; g_b4[384+i] = bs[i];
    }
}

// ---------------- fused LN kernels ----------------
__global__ void k_node_prep(const float* __restrict__ x, const float* __restrict__ demb,
                            const float* __restrict__ g, const float* __restrict__ b) {
    int row = blockIdx.x * 8 + (threadIdx.x >> 5);
    if (row >= NN) return;
    int lane = threadIdx.x & 31;
    int d = g_deg[row]; if (d > 255) d = 255;
    float4 xv = *(const float4*)(x + (size_t)row*DIM + lane*4);
    float4 dv = *(const float4*)(demb + (size_t)d*DIM + lane*4);
    float4 xi = make_float4(xv.x+dv.x, xv.y+dv.y, xv.z+dv.z, xv.w+dv.w);
    *(float4*)(g_xin + (size_t)row*DIM + lane*4) = xi;
    float m = warp_sum(xi.x+xi.y+xi.z+xi.w) * (1.0f/128.0f);
    float4 dd = make_float4(xi.x-m, xi.y-m, xi.z-m, xi.w-m);
    float var = warp_sum(dd.x*dd.x+dd.y*dd.y+dd.z*dd.z+dd.w*dd.w) * (1.0f/128.0f);
    float inv = rsqrtf(var + 1e-5f);
    float4 gv = *(const float4*)(g + lane*4);
    float4 bv = *(const float4*)(b + lane*4);
    *(float4*)(g_h + (size_t)row*DIM + lane*4) =
        make_float4(dd.x*inv*gv.x+bv.x, dd.y*inv*gv.y+bv.y, dd.z*inv*gv.z+bv.z, dd.w*inv*gv.w+bv.w);
}

// x_attn = x_in + agg/denom + skip; h2 = LN(x_attn)
__global__ void k_node_post(const float* __restrict__ g, const float* __restrict__ b) {
    int row = blockIdx.x * 8 + (threadIdx.x >> 5);
    if (row >= NN) return;
    int lane = threadIdx.x & 31;
    float dn = g_denom[(size_t)row*NH + (lane >> 2)];
    float rd = (dn != 0.0f) ? (1.0f / dn) : 0.0f;
    float4 xi = *(const float4*)(g_xin + (size_t)row*DIM + lane*4);
    float4 ag = *(const float4*)(g_agg + (size_t)row*DIM + lane*4);
    float4 sk = *(const float4*)(g_qkvs + (size_t)row*512 + 384 + lane*4);
    float4 xa = make_float4(xi.x+ag.x*rd+sk.x, xi.y+ag.y*rd+sk.y,
                            xi.z+ag.z*rd+sk.z, xi.w+ag.w*rd+sk.w);
    *(float4*)(g_xattn + (size_t)row*DIM + lane*4) = xa;
    float m = warp_sum(xa.x+xa.y+xa.z+xa.w) * (1.0f/128.0f);
    float4 dd = make_float4(xa.x-m, xa.y-m, xa.z-m, xa.w-m);
    float var = warp_sum(dd.x*dd.x+dd.y*dd.y+dd.z*dd.z+dd.w*dd.w) * (1.0f/128.0f);
    float inv = rsqrtf(var + 1e-5f);
    float4 gv = *(const float4*)(g + lane*4);
    float4 bv = *(const float4*)(b + lane*4);
    *(float4*)(g_h2 + (size_t)row*DIM + lane*4) =
        make_float4(dd.x*inv*gv.x+bv.x, dd.y*inv*gv.y+bv.y, dd.z*inv*gv.z+bv.z, dd.w*inv*gv.w+bv.w);
}

// ---------------- generic tf32 mma GEMM: 128x128 tile, cp.async double-buffered ----------------
// MODE 0:+bias  1:+bias,GELU  2:+bias+res + fused row-LN -> xn_out  3:plain(no bias)
template<int MODE>
__global__ void __launch_bounds__(256, 2)
k_gemm_mma(const float* __restrict__ A, int lda,
           const float* __restrict__ B, int ldb,
           const float* __restrict__ bias,
           float* __restrict__ Co, int ldc,
           const float* __restrict__ res, int ldr,
           int M, int K,
           const float* __restrict__ lng, const float* __restrict__ lnb,
           float* __restrict__ xn_out) {
    extern __shared__ uint32_t smu[];
    uint32_t (*Ab0)[ALD] = (uint32_t(*)[ALD])smu;
    uint32_t (*Ab1)[ALD] = (uint32_t(*)[ALD])(smu + AOFF);
    uint32_t (*Bb0)[BLD] = (uint32_t(*)[BLD])(smu + 2*AOFF);
    uint32_t (*Bb1)[BLD] = (uint32_t(*)[BLD])(smu + 2*AOFF + BOFF);
    float    (*st)[132]  = (float(*)[132])smu;     // MODE 2 staging overlay

    const int m0 = blockIdx.y * 128, n0 = blockIdx.x * 128;
    const int tid = threadIdx.x;
    const int warp = tid >> 5, lane = tid & 31;
    const int wm = warp >> 1, wn = warp & 1;
    const int Mb = wm * 32, Nb = wn * 64;
    const int lg = lane >> 2, lt = lane & 3;
    const int lr = tid >> 1, lc = (tid & 1) * 16;
    const int kb = tid >> 3, cb = (tid & 7) * 16;

    const uint32_t aD[2] = { (uint32_t)__cvta_generic_to_shared(&Ab0[lr][lc]),
                             (uint32_t)__cvta_generic_to_shared(&Ab1[lr][lc]) };
    const uint32_t bD[2] = { (uint32_t)__cvta_generic_to_shared(&Bb0[kb][cb]),
                             (uint32_t)__cvta_generic_to_shared(&Bb1[kb][cb]) };
    const bool aIn = (m0 + lr) < M;

    auto issue = [&](int c, int buf) {
        int k0 = c * 32;
        if (aIn) {
            const float* ap = A + (size_t)(m0 + lr)*lda + k0 + lc;
#pragma unroll
            for (int i = 0; i < 4; i++) cp16(aD[buf] + i*16, ap + i*4);
        } else {
            uint32_t (*Ax)[ALD] = buf ? Ab1 : Ab0;
#pragma unroll
            for (int i = 0; i < 4; i++)
                *(float4*)&Ax[lr][lc + i*4] = make_float4(0,0,0,0);
        }
        const float* bp = B + (size_t)(k0 + kb)*ldb + n0 + cb;
#pragma unroll
        for (int i = 0; i < 4; i++) cp16(bD[buf] + i*16, bp + i*4);
        cp_commit();
    };

    float acc[2][8][4] = {};
    const int NC = K >> 5;
    issue(0, 0);
    for (int c = 0; c < NC; c++) {
        int cur = c & 1;
        if (c + 1 < NC) { issue(c+1, cur ^ 1); cp_wait<1>(); }
        else cp_wait<0>();
        __syncthreads();
        uint32_t (*Ac)[ALD] = cur ? Ab1 : Ab0;
        uint32_t (*Bc)[BLD] = cur ? Bb1 : Bb0;
#pragma unroll
        for (int kq = 0; kq < 4; kq++) {
            const int kc = kq * 8;
            uint32_t b0[8], b1[8];
#pragma unroll
            for (int nt = 0; nt < 8; nt++) {
                int colB = Nb + nt*8 + lg;
                b0[nt] = Bc[kc + lt][colB];
                b1[nt] = Bc[kc + 4 + lt][colB];
            }
#pragma unroll
            for (int mt = 0; mt < 2; mt++) {
                int rb = Mb + mt*16;
                uint32_t a0 = Ac[rb + lg    ][kc + lt];
                uint32_t a1 = Ac[rb + 8 + lg][kc + lt];
                uint32_t a2 = Ac[rb + lg    ][kc + 4 + lt];
                uint32_t a3 = Ac[rb + 8 + lg][kc + 4 + lt];
#pragma unroll
                for (int nt = 0; nt < 8; nt++)
                    mma_tf32(acc[mt][nt], a0, a1, a2, a3, b0[nt], b1[nt]);
            }
        }
        __syncthreads();
    }

    if (MODE != 2) {
#pragma unroll
        for (int mt = 0; mt < 2; mt++) {
            int r0 = m0 + Mb + mt*16 + lg;
#pragma unroll
            for (int nt = 0; nt < 8; nt++) {
                int cg = n0 + Nb + nt*8 + 2*lt;
                float2 bb = (MODE == 3) ? make_float2(0.0f, 0.0f)
                                        : *(const float2*)(bias + cg);
#pragma unroll
                for (int hrow = 0; hrow < 2; hrow++) {
                    int m = r0 + hrow*8;
                    if (m >= M) continue;
                    float cx = acc[mt][nt][hrow*2 + 0] + bb.x;
                    float cy = acc[mt][nt][hrow*2 + 1] + bb.y;
                    if (MODE == 1) { cx = gelu_erf(cx); cy = gelu_erf(cy); }
                    *(float2*)(Co + (size_t)m*ldc + cg) = make_float2(cx, cy);
                }
            }
        }
    } else {
        // MODE 2: bias + residual -> stage to smem, then per-row LN -> Co (x_new) and xn_out
#pragma unroll
        for (int mt = 0; mt < 2; mt++) {
            int rloc = Mb + mt*16 + lg;
#pragma unroll
            for (int nt = 0; nt < 8; nt++) {
                int cl = Nb + nt*8 + 2*lt;
                int cg = n0 + cl;
                float2 bb = *(const float2*)(bias + cg);
#pragma unroll
                for (int hrow = 0; hrow < 2; hrow++) {
                    int r = rloc + hrow*8;
                    int m = m0 + r;
                    float cx = acc[mt][nt][hrow*2 + 0] + bb.x;
                    float cy = acc[mt][nt][hrow*2 + 1] + bb.y;
                    if (m < M) {
                        float2 rr = *(const float2*)(res + (size_t)m*ldr + cg);
                        cx += rr.x; cy += rr.y;
                    }
                    *(float2*)&st[r][cl] = make_float2(cx, cy);
                }
            }
        }
        __syncthreads();
#pragma unroll
        for (int rr = 0; rr < 16; rr++) {
            int r = warp * 16 + rr;
            int m = m0 + r;
            if (m >= M) continue;
            float4 xv = *(const float4*)&st[r][lane*4];
            float mn = warp_sum(xv.x+xv.y+xv.z+xv.w) * (1.0f/128.0f);
            float4 dd = make_float4(xv.x-mn, xv.y-mn, xv.z-mn, xv.w-mn);
            float var = warp_sum(dd.x*dd.x+dd.y*dd.y+dd.z*dd.z+dd.w*dd.w) * (1.0f/128.0f);
            float inv = rsqrtf(var + 1e-5f);
            float4 gv = *(const float4*)(lng + lane*4);
            float4 bv = *(const float4*)(lnb + lane*4);
            *(float4*)(Co + (size_t)m*ldc + lane*4) = xv;
            *(float4*)(xn_out + (size_t)m*DIM + lane*4) =
                make_float4(dd.x*inv*gv.x+bv.x, dd.y*inv*gv.y+bv.y,
                            dd.z*inv*gv.z+bv.z, dd.w*inv*gv.w+bv.w);
        }
    }
}

// ---------------- fused edge-proj + attention (cp.async double-buffered) ----------------
__global__ void __launch_bounds__(256, 2)
k_eattn(const int* __restrict__ src, const int* __restrict__ dst,
        const float* __restrict__ ea, const float* __restrict__ We) {
    extern __shared__ uint32_t smu[];
    uint32_t (*Ab0)[ALD] = (uint32_t(*)[ALD])smu;
    uint32_t (*Ab1)[ALD] = (uint32_t(*)[ALD])(smu + AOFF);
    uint32_t (*Bb0)[BLD] = (uint32_t(*)[BLD])(smu + 2*AOFF);
    uint32_t (*Bb1)[BLD] = (uint32_t(*)[BLD])(smu + 2*AOFF + BOFF);
    float    (*et)[132]  = (float(*)[132])smu;
    __shared__ int sidx[128], didx[128];

    const int tid  = threadIdx.x;
    const int warp = tid >> 5, lane = tid & 31;
    const int e0 = blockIdx.x * 128;
    if (tid < 128) { sidx[tid] = src[e0+tid]; didx[tid] = dst[e0+tid]; }
    __syncthreads();

    const int wm = warp >> 1, wn = warp & 1;
    const int Mb = wm * 32, Nb = wn * 64;
    const int lg = lane >> 2, lt = lane & 3;
    const int lr = tid >> 1, lc = (tid & 1) * 16;
    const int kb = tid >> 3, cb = (tid & 7) * 16;

    const uint32_t aD[2] = { (uint32_t)__cvta_generic_to_shared(&Ab0[lr][lc]),
                             (uint32_t)__cvta_generic_to_shared(&Ab1[lr][lc]) };
    const uint32_t bD[2] = { (uint32_t)__cvta_generic_to_shared(&Bb0[kb][cb]),
                             (uint32_t)__cvta_generic_to_shared(&Bb1[kb][cb]) };

    auto issue = [&](int c, int buf) {
        int k0 = c * 32;
        const float* ap = ea + (size_t)(e0 + lr)*64 + k0 + lc;
#pragma unroll
        for (int i = 0; i < 4; i++) cp16(aD[buf] + i*16, ap + i*4);
        const float* bp = We + (size_t)(k0 + kb)*128 + cb;
#pragma unroll
        for (int i = 0; i < 4; i++) cp16(bD[buf] + i*16, bp + i*4);
        cp_commit();
    };

    float acc[2][8][4] = {};
    issue(0, 0);
#pragma unroll
    for (int c = 0; c < 2; c++) {
        int cur = c & 1;
        if (c == 0) { issue(1, 1); cp_wait<1>(); }
        else cp_wait<0>();
        __syncthreads();
        uint32_t (*Ac)[ALD] = cur ? Ab1 : Ab0;
        uint32_t (*Bc)[BLD] = cur ? Bb1 : Bb0;
#pragma unroll
        for (int kq = 0; kq < 4; kq++) {
            const int kc = kq * 8;
            uint32_t b0[8], b1[8];
#pragma unroll
            for (int nt = 0; nt < 8; nt++) {
                int colB = Nb + nt*8 + lg;
                b0[nt] = Bc[kc + lt][colB];
                b1[nt] = Bc[kc + 4 + lt][colB];
            }
#pragma unroll
            for (int mt = 0; mt < 2; mt++) {
                int rb = Mb + mt*16;
                uint32_t a0 = Ac[rb + lg    ][kc + lt];
                uint32_t a1 = Ac[rb + 8 + lg][kc + lt];
                uint32_t a2 = Ac[rb + lg    ][kc + 4 + lt];
                uint32_t a3 = Ac[rb + 8 + lg][kc + 4 + lt];
#pragma unroll
                for (int nt = 0; nt < 8; nt++)
                    mma_tf32(acc[mt][nt], a0, a1, a2, a3, b0[nt], b1[nt]);
            }
        }
        __syncthreads();
    }

#pragma unroll
    for (int mt = 0; mt < 2; mt++) {
        int r0 = Mb + mt*16 + lg;
#pragma unroll
        for (int nt = 0; nt < 8; nt++) {
            int c0 = Nb + nt*8 + 2*lt;
            *(float2*)&et[r0][c0]     = make_float2(acc[mt][nt][0], acc[mt][nt][1]);
            *(float2*)&et[r0 + 8][c0] = make_float2(acc[mt][nt][2], acc[mt][nt][3]);
        }
    }
    __syncthreads();

    // attention: warp-per-edge, batched 4 edges per group for load MLP
    const int c4 = lane * 4;
#pragma unroll
    for (int grp = 0; grp < 4; grp++) {
        int base = warp * 16 + grp * 4;
        float4 q[4], k[4], v[4], ev[4];
        int dd[4];
        float pe[4];
#pragma unroll
        for (int j = 0; j < 4; j++) {
            int el = base + j;
            int s = sidx[el]; dd[j] = didx[el];
            q[j]  = *(const float4*)(g_qkvs + (size_t)dd[j]*512 + c4);
            k[j]  = *(const float4*)(g_qkvs + (size_t)s*512 + 128 + c4);
            v[j]  = *(const float4*)(g_qkvs + (size_t)s*512 + 256 + c4);
            ev[j] = *(const float4*)&et[el][c4];
        }
#pragma unroll
        for (int j = 0; j < 4; j++) {
            float part = q[j].x*(k[j].x+ev[j].x) + q[j].y*(k[j].y+ev[j].y)
                       + q[j].z*(k[j].z+ev[j].z) + q[j].w*(k[j].w+ev[j].w);
            part += __shfl_xor_sync(0xffffffffu, part, 1);
            part += __shfl_xor_sync(0xffffffffu, part, 2);
            pe[j] = expf(part * 0.25f);
        }
#pragma unroll
        for (int j = 0; j < 4; j++) {
            float m0 = pe[j]*(v[j].x+ev[j].x), m1 = pe[j]*(v[j].y+ev[j].y);
            float m2 = pe[j]*(v[j].z+ev[j].z), m3 = pe[j]*(v[j].w+ev[j].w);
            float* o = g_agg + (size_t)dd[j]*128 + c4;
            asm volatile("red.global.add.v4.f32 [%0], {%1,%2,%3,%4};"
                         :: "l"(o), "f"(m0), "f"(m1), "f"(m2), "f"(m3) : "memory");
            if ((lane & 3) == 0) {
                float* dn = g_denom + (size_t)dd[j]*NH + (lane >> 2);
                asm volatile("red.global.add.f32 [%0], %1;" :: "l"(dn), "f"(pe[j]) : "memory");
            }
        }
    }
}

// ---------------- edge update v2: factored GEMM (K=64 only) + P12 gather epilogue ----------------
// raw_full[e][c] = relu( (ea[e]@Wea)[c] + P12[src][c] + P12[dst][128+c] + bias[c] )
// then t = ea + raw_full[0:64]*sigmoid(raw_full[64:128]); LN(64) -> out
__global__ void __launch_bounds__(256, 2)
k_edge2(const int* __restrict__ src, const int* __restrict__ dst,
        const float* __restrict__ ea,
        const float* __restrict__ Wea, const float* __restrict__ bvec,
        const float* __restrict__ eg, const float* __restrict__ ebias,
        float* __restrict__ out) {
    extern __shared__ uint32_t smu[];
    uint32_t (*Ab0)[ALD] = (uint32_t(*)[ALD])smu;
    uint32_t (*Ab1)[ALD] = (uint32_t(*)[ALD])(smu + AOFF);
    uint32_t (*Bb0)[BLD] = (uint32_t(*)[BLD])(smu + 2*AOFF);
    uint32_t (*Bb1)[BLD] = (uint32_t(*)[BLD])(smu + 2*AOFF + BOFF);
    float    (*raw)[132] = (float(*)[132])smu;     // overlay after GEMM (acc only, no relu yet)
    __shared__ int sidx[128], didx[128];

    const int tid  = threadIdx.x;
    const int warp = tid >> 5, lane = tid & 31;
    const int e0 = blockIdx.x * 128;
    if (tid < 128) { sidx[tid] = src[e0+tid]; didx[tid] = dst[e0+tid]; }
    __syncthreads();

    const int wm = warp >> 1, wn = warp & 1;
    const int Mb = wm * 32, Nb = wn * 64;
    const int lg = lane >> 2, lt = lane & 3;
    const int lr = tid >> 1, lc = (tid & 1) * 16;
    const int kb = tid >> 3, cb = (tid & 7) * 16;

    const uint32_t aD[2] = { (uint32_t)__cvta_generic_to_shared(&Ab0[lr][lc]),
                             (uint32_t)__cvta_generic_to_shared(&Ab1[lr][lc]) };
    const uint32_t bD[2] = { (uint32_t)__cvta_generic_to_shared(&Bb0[kb][cb]),
                             (uint32_t)__cvta_generic_to_shared(&Bb1[kb][cb]) };

    auto issue = [&](int c, int buf) {
        int k0 = c * 32;
        const float* ap = ea + (size_t)(e0 + lr)*64 + k0 + lc;
#pragma unroll
        for (int i = 0; i < 4; i++) cp16(aD[buf] + i*16, ap + i*4);
        const float* bp = Wea + (size_t)(k0 + kb)*128 + cb;
#pragma unroll
        for (int i = 0; i < 4; i++) cp16(bD[buf] + i*16, bp + i*4);
        cp_commit();
    };

    float acc[2][8][4] = {};
    issue(0, 0);
#pragma unroll
    for (int c = 0; c < 2; c++) {
        int cur = c & 1;
        if (c == 0) { issue(1, 1); cp_wait<1>(); }
        else cp_wait<0>();
        __syncthreads();
        uint32_t (*Ac)[ALD] = cur ? Ab1 : Ab0;
        uint32_t (*Bc)[BLD] = cur ? Bb1 : Bb0;
#pragma unroll
        for (int kq = 0; kq < 4; kq++) {
            const int kc = kq * 8;
            uint32_t b0[8], b1[8];
#pragma unroll
            for (int nt = 0; nt < 8; nt++) {
                int colB = Nb + nt*8 + lg;
                b0[nt] = Bc[kc + lt][colB];
                b1[nt] = Bc[kc + 4 + lt][colB];
            }
#pragma unroll
            for (int mt = 0; mt < 2; mt++) {
                int rb = Mb + mt*16;
                uint32_t a0 = Ac[rb + lg    ][kc + lt];
                uint32_t a1 = Ac[rb + 8 + lg][kc + lt];
                uint32_t a2 = Ac[rb + lg    ][kc + 4 + lt];
                uint32_t a3 = Ac[rb + 8 + lg][kc + 4 + lt];
#pragma unroll
                for (int nt = 0; nt < 8; nt++)
                    mma_tf32(acc[mt][nt], a0, a1, a2, a3, b0[nt], b1[nt]);
            }
        }
        __syncthreads();
    }

    // stage acc (NO bias/relu yet) to raw smem
#pragma unroll
    for (int mt = 0; mt < 2; mt++) {
        int r0 = Mb + mt*16 + lg;
#pragma unroll
        for (int nt = 0; nt < 8; nt++) {
            int c0 = Nb + nt*8 + 2*lt;
            *(float2*)&raw[r0][c0]     = make_float2(acc[mt][nt][0], acc[mt][nt][1]);
            *(float2*)&raw[r0 + 8][c0] = make_float2(acc[mt][nt][2], acc[mt][nt][3]);
        }
    }
    __syncthreads();

    // epilogue: add P12[src] + P12[dst] + bias, relu, gate, LN(64)
#pragma unroll
    for (int half = 0; half < 2; half++) {
        int r = (tid >> 2) + half * 64;
        int q = tid & 3;
        const float* ps = g_P12 + (size_t)sidx[r]*256;         // src contribution [0:128)
        const float* pd = g_P12 + (size_t)didx[r]*256 + 128;   // dst contribution [0:128)
        float t[16]; float s = 0.0f;
#pragma unroll
        for (int i4 = 0; i4 < 16; i4 += 4) {
            int cc = q*16 + i4;
            float4 e4  = *(const float4*)(ea + (size_t)(e0+r)*64 + cc);
            float4 rD  = *(const float4*)&raw[r][cc];
            float4 rG  = *(const float4*)&raw[r][64+cc];
            float4 p1D = *(const float4*)(ps + cc);
            float4 p1G = *(const float4*)(ps + 64 + cc);
            float4 p2D = *(const float4*)(pd + cc);
            float4 p2G = *(const float4*)(pd + 64 + cc);
            float4 bD  = *(const float4*)(bvec + cc);
            float4 bG  = *(const float4*)(bvec + 64 + cc);
            float d0 = fmaxf(rD.x + p1D.x + p2D.x + bD.x, 0.0f);
            float d1 = fmaxf(rD.y + p1D.y + p2D.y + bD.y, 0.0f);
            float d2 = fmaxf(rD.z + p1D.z + p2D.z + bD.z, 0.0f);
            float d3 = fmaxf(rD.w + p1D.w + p2D.w + bD.w, 0.0f);
            float g0 = fmaxf(rG.x + p1G.x + p2G.x + bG.x, 0.0f);
            float g1 = fmaxf(rG.y + p1G.y + p2G.y + bG.y, 0.0f);
            float g2 = fmaxf(rG.z + p1G.z + p2G.z + bG.z, 0.0f);
            float g3 = fmaxf(rG.w + p1G.w + p2G.w + bG.w, 0.0f);
            t[i4+0] = e4.x + d0 / (1.0f + expf(-g0));
            t[i4+1] = e4.y + d1 / (1.0f + expf(-g1));
            t[i4+2] = e4.z + d2 / (1.0f + expf(-g2));
            t[i4+3] = e4.w + d3 / (1.0f + expf(-g3));
            s += t[i4+0] + t[i4+1] + t[i4+2] + t[i4+3];
        }
        s += __shfl_xor_sync(0xffffffffu, s, 1);
        s += __shfl_xor_sync(0xffffffffu, s, 2);
        float m = s * (1.0f/64.0f);
        float vs = 0.0f;
#pragma unroll
        for (int i = 0; i < 16; i++) { float dd = t[i] - m; vs += dd*dd; }
        vs += __shfl_xor_sync(0xffffffffu, vs, 1);
        vs += __shfl_xor_sync(0xffffffffu, vs, 2);
        float inv = rsqrtf(vs * (1.0f/64.0f) + 1e-5f);
#pragma unroll
        for (int i4 = 0; i4 < 16; i4 += 4) {
            int cc = q*16 + i4;
            float4 gv = *(const float4*)(eg + cc);
            float4 bb = *(const float4*)(ebias + cc);
            *(float4*)(out + (size_t)(e0+r)*64 + cc) =
                make_float4((t[i4+0]-m)*inv*gv.x+bb.x, (t[i4+1]-m)*inv*gv.y+bb.y,
                            (t[i4+2]-m)*inv*gv.z+bb.z, (t[i4+3]-m)*inv*gv.w+bb.w);
        }
    }
}

// ---------------- launcher ----------------
extern "C" void kernel_launch(void* const* d_in, const int* in_sizes, int n_in,
                              void* d_out, int out_size) {
    const float* x     = (const float*)d_in[0];
    const int*   ei    = (const int*)  d_in[1];
    const float* ea    = (const float*)d_in[2];
    const float* demb  = (const float*)d_in[3];
    const float* ng    = (const float*)d_in[4];
    const float* nbv   = (const float*)d_in[5];
    const float* Wq    = (const float*)d_in[6];
    const float* bq    = (const float*)d_in[7];
    const float* Wk    = (const float*)d_in[8];
    const float* bk    = (const float*)d_in[9];
    const float* Wv    = (const float*)d_in[10];
    const float* bv    = (const float*)d_in[11];
    const float* We    = (const float*)d_in[12];
    const float* Wskip = (const float*)d_in[13];
    const float* bskip = (const float*)d_in[14];
    const float* W1    = (const float*)d_in[15];
    const float* b1    = (const float*)d_in[16];
    const float* W2    = (const float*)d_in[17];
    const float* b2    = (const float*)d_in[18];
    const float* eung  = (const float*)d_in[19];
    const float* eunb  = (const float*)d_in[20];
    const float* euW   = (const float*)d_in[21];
    const float* eub   = (const float*)d_in[22];
    const float* eueg  = (const float*)d_in[23];
    const float* eueb  = (const float*)d_in[24];
    float* out = (float*)d_out;

    const int* src = ei;
    const int* dst = ei + EE;

    static float *p_h = nullptr, *p_qkvs = nullptr,
                 *p_h2 = nullptr, *p_ffn1 = nullptr, *p_xattn = nullptr,
                 *p_W4 = nullptr, *p_b4 = nullptr, *p_xn = nullptr,
                 *p_Wp = nullptr, *p_P12 = nullptr;
    static bool inited = false;
    if (!inited) {
        cudaGetSymbolAddress((void**)&p_h,     g_h);
        cudaGetSymbolAddress((void**)&p_qkvs,  g_qkvs);
        cudaGetSymbolAddress((void**)&p_h2,    g_h2);
        cudaGetSymbolAddress((void**)&p_ffn1,  g_ffn1);
        cudaGetSymbolAddress((void**)&p_xattn, g_xattn);
        cudaGetSymbolAddress((void**)&p_W4,    g_W4);
        cudaGetSymbolAddress((void**)&p_b4,    g_b4);
        cudaGetSymbolAddress((void**)&p_xn,    g_xn);
        cudaGetSymbolAddress((void**)&p_Wp,    g_Wp);
        cudaGetSymbolAddress((void**)&p_P12,   g_P12);
        cudaFuncSetAttribute(k_gemm_mma<0>, cudaFuncAttributeMaxDynamicSharedMemorySize, MMA_SMEM);
        cudaFuncSetAttribute(k_gemm_mma<1>, cudaFuncAttributeMaxDynamicSharedMemorySize, MMA_SMEM);
        cudaFuncSetAttribute(k_gemm_mma<2>, cudaFuncAttributeMaxDynamicSharedMemorySize, MMA_SMEM);
        cudaFuncSetAttribute(k_gemm_mma<3>, cudaFuncAttributeMaxDynamicSharedMemorySize, MMA_SMEM);
        cudaFuncSetAttribute(k_eattn,       cudaFuncAttributeMaxDynamicSharedMemorySize, MMA_SMEM);
        cudaFuncSetAttribute(k_edge2,       cudaFuncAttributeMaxDynamicSharedMemorySize, MMA_SMEM);
        inited = true;
    }

    const int MB = (NN + 127) / 128;   // 391

    k_init<<<2048, 256>>>();
    k_deg<<<(EE + 255)/256, 256>>>(src);
    k_pack<<<64, 256>>>(Wq, Wk, Wv, Wskip, bq, bk, bv, bskip, euW);
    k_node_prep<<<(NN + 7)/8, 256>>>(x, demb, ng, nbv);

    // fused QKV+skip: [50000x128] @ [128x512]  (tf32 mma)
    k_gemm_mma<0><<<dim3(4, MB), 256, MMA_SMEM>>>(p_h, 128, p_W4, 512, p_b4, p_qkvs, 512,
                                                  nullptr, 0, NN, 128, nullptr, nullptr, nullptr);

    // fused edge-proj + attention (single pass; unnormalized agg + denom)
    k_eattn<<<EE/128, 256, MMA_SMEM>>>(src, dst, ea, We);

    k_node_post<<<(NN + 7)/8, 256>>>(ng, nbv);

    // FFN (tf32 mma); FFN2 fuses the eu-LN producing g_xn
    k_gemm_mma<1><<<dim3(4, MB), 256, MMA_SMEM>>>(p_h2, 128, W1, 512, b1, p_ffn1, 512,
                                                  nullptr, 0, NN, 128, nullptr, nullptr, nullptr);
    k_gemm_mma<2><<<dim3(1, MB), 256, MMA_SMEM>>>(p_ffn1, 512, W2, 128, b2, out, 128,
                                                  p_xattn, 128, NN, 512, eung, eunb, p_xn);

    // node-side factor of the edge-update GEMM: P12 = xn @ [Wsrc | Wdst]
    k_gemm_mma<3><<<dim3(2, MB), 256, MMA_SMEM>>>(p_xn, 128, p_Wp, 256, nullptr, p_P12, 256,
                                                  nullptr, 0, NN, 128, nullptr, nullptr, nullptr);

    // edge update: ea-only GEMM (K=64) + P12 gather epilogue
    k_edge2<<<EE/128, 256, MMA_SMEM>>>(src, dst, ea, euW + (size_t)256*128, eub,
                                       eueg, eueb, out + (size_t)NN*DIM);
}

// round 13
// speedup vs baseline: 1.1708x; 1.1708x over previous
#include <cuda_runtime.h>
#include <math.h>
#include <stdint.h>

// ---------------- problem constants ----------------
constexpr int NN   = 50000;
constexpr int EE   = 800000;
constexpr int DIM  = 128;
constexpr int NH   = 8;
constexpr int HID  = 512;

// ---------------- scratch ----------------
__device__ float g_xin  [(size_t)NN*DIM];
__device__ float g_h    [(size_t)NN*DIM];
__device__ float g_qkvs [(size_t)NN*4*DIM];   // q[0:128) k[128:256) v[256:384) skip[384:512)
__device__ float g_denom[(size_t)NN*NH];
__device__ float g_agg  [(size_t)NN*DIM];     // UNNORMALIZED sum of pe*(v+e)
__device__ float g_xattn[(size_t)NN*DIM];
__device__ float g_h2   [(size_t)NN*DIM];
__device__ float g_ffn1 [(size_t)NN*HID];
__device__ float g_xn   [(size_t)NN*DIM];
__device__ float g_W4   [(size_t)DIM*512];
__device__ float g_b4   [512];
__device__ int   g_deg  [NN];

// ---------------- helpers ----------------
__device__ __forceinline__ float warp_sum(float v) {
#pragma unroll
    for (int o = 16; o > 0; o >>= 1) v += __shfl_xor_sync(0xffffffffu, v, o);
    return v;
}
__device__ __forceinline__ void mma_tf32(float* c,
                                         uint32_t a0, uint32_t a1, uint32_t a2, uint32_t a3,
                                         uint32_t b0, uint32_t b1) {
    asm volatile("mma.sync.aligned.m16n8k8.row.col.f32.tf32.tf32.f32 "
                 "{%0,%1,%2,%3}, {%4,%5,%6,%7}, {%8,%9}, {%0,%1,%2,%3};"
                 : "+f"(c[0]), "+f"(c[1]), "+f"(c[2]), "+f"(c[3])
                 : "r"(a0), "r"(a1), "r"(a2), "r"(a3), "r"(b0), "r"(b1));
}
__device__ __forceinline__ float gelu_erf(float v) {
    return 0.5f * v * (1.0f + erff(v * 0.70710678118654752f));
}
__device__ __forceinline__ void cp16(uint32_t d, const float* g) {
    asm volatile("cp.async.cg.shared.global [%0], [%1], 16;" :: "r"(d), "l"(g) : "memory");
}
__device__ __forceinline__ void cp_commit() {
    asm volatile("cp.async.commit_group;" ::: "memory");
}
template<int N> __device__ __forceinline__ void cp_wait() {
    asm volatile("cp.async.wait_group %0;" :: "n"(N) : "memory");
}

// smem tile geometry (shared by all mma kernels)
constexpr int ALD = 36;    // A smem ld (mod 32 = 4 -> conflict-free frag reads)
constexpr int BLD = 136;   // B smem ld (mod 32 = 8)
constexpr int AOFF = 128*ALD;
constexpr int BOFF = 32*BLD;
constexpr int TILE_SMEM_U32 = 2*AOFF + 2*BOFF;   // 17920 u32 = 71680 B
constexpr int MMA_SMEM = TILE_SMEM_U32 * 4;

// ---------------- setup: zero scratch + pack weights (merged, order-independent) ----------------
__global__ void k_setup(const float* __restrict__ Wq, const float* __restrict__ Wk,
                        const float* __restrict__ Wv, const float* __restrict__ Ws,
                        const float* __restrict__ bq, const float* __restrict__ bk,
                        const float* __restrict__ bv, const float* __restrict__ bs) {
    int i  = blockIdx.x * blockDim.x + threadIdx.x;
    int st = gridDim.x * blockDim.x;
    for (int j = i; j < NN*DIM; j += st) g_agg[j] = 0.0f;
    for (int j = i; j < NN*NH;  j += st) g_denom[j] = 0.0f;
    for (int j = i; j < NN;     j += st) g_deg[j] = 0;
    if (i < DIM*DIM) {
        int r = i >> 7, c = i & 127;
        g_W4[(size_t)r*512 +       c] = Wq[i];
        g_W4[(size_t)r*512 + 128 + c] = Wk[i];
        g_W4[(size_t)r*512 + 256 + c] = Wv[i];
        g_W4[(size_t)r*512 + 384 + c] = Ws[i];
    }
    if (i < 128) {
        g_b4[i] = bq[i]; g_b4[128+i] = bk[i]; g_b4[256+i] = bv[i]; g_b4[384+i] = bs[i];
    }
}
__global__ void k_deg(const int* __restrict__ src) {
    int i = blockIdx.x * blockDim.x + threadIdx.x;
    if (i < EE) atomicAdd(&g_deg[src[i]], 1);
}

// ---------------- fused LN kernels ----------------
__global__ void k_node_prep(const float* __restrict__ x, const float* __restrict__ demb,
                            const float* __restrict__ g, const float* __restrict__ b) {
    int row = blockIdx.x * 8 + (threadIdx.x >> 5);
    if (row >= NN) return;
    int lane = threadIdx.x & 31;
    int d = g_deg[row]; if (d > 255) d = 255;
    float4 xv = *(const float4*)(x + (size_t)row*DIM + lane*4);
    float4 dv = *(const float4*)(demb + (size_t)d*DIM + lane*4);
    float4 xi = make_float4(xv.x+dv.x, xv.y+dv.y, xv.z+dv.z, xv.w+dv.w);
    *(float4*)(g_xin + (size_t)row*DIM + lane*4) = xi;
    float m = warp_sum(xi.x+xi.y+xi.z+xi.w) * (1.0f/128.0f);
    float4 dd = make_float4(xi.x-m, xi.y-m, xi.z-m, xi.w-m);
    float var = warp_sum(dd.x*dd.x+dd.y*dd.y+dd.z*dd.z+dd.w*dd.w) * (1.0f/128.0f);
    float inv = rsqrtf(var + 1e-5f);
    float4 gv = *(const float4*)(g + lane*4);
    float4 bv = *(const float4*)(b + lane*4);
    *(float4*)(g_h + (size_t)row*DIM + lane*4) =
        make_float4(dd.x*inv*gv.x+bv.x, dd.y*inv*gv.y+bv.y, dd.z*inv*gv.z+bv.z, dd.w*inv*gv.w+bv.w);
}

// x_attn = x_in + agg/denom + skip; h2 = LN(x_attn)
__global__ void k_node_post(const float* __restrict__ g, const float* __restrict__ b) {
    int row = blockIdx.x * 8 + (threadIdx.x >> 5);
    if (row >= NN) return;
    int lane = threadIdx.x & 31;
    float dn = g_denom[(size_t)row*NH + (lane >> 2)];
    float rd = (dn != 0.0f) ? (1.0f / dn) : 0.0f;
    float4 xi = *(const float4*)(g_xin + (size_t)row*DIM + lane*4);
    float4 ag = *(const float4*)(g_agg + (size_t)row*DIM + lane*4);
    float4 sk = *(const float4*)(g_qkvs + (size_t)row*512 + 384 + lane*4);
    float4 xa = make_float4(xi.x+ag.x*rd+sk.x, xi.y+ag.y*rd+sk.y,
                            xi.z+ag.z*rd+sk.z, xi.w+ag.w*rd+sk.w);
    *(float4*)(g_xattn + (size_t)row*DIM + lane*4) = xa;
    float m = warp_sum(xa.x+xa.y+xa.z+xa.w) * (1.0f/128.0f);
    float4 dd = make_float4(xa.x-m, xa.y-m, xa.z-m, xa.w-m);
    float var = warp_sum(dd.x*dd.x+dd.y*dd.y+dd.z*dd.z+dd.w*dd.w) * (1.0f/128.0f);
    float inv = rsqrtf(var + 1e-5f);
    float4 gv = *(const float4*)(g + lane*4);
    float4 bv = *(const float4*)(b + lane*4);
    *(float4*)(g_h2 + (size_t)row*DIM + lane*4) =
        make_float4(dd.x*inv*gv.x+bv.x, dd.y*inv*gv.y+bv.y, dd.z*inv*gv.z+bv.z, dd.w*inv*gv.w+bv.w);
}

// ---------------- generic tf32 mma GEMM: 128x128 tile, cp.async double-buffered ----------------
// MODE 0:+bias  1:+bias,GELU  2:+bias+res + fused row-LN -> xn_out (also writes Co)
template<int MODE>
__global__ void __launch_bounds__(256, 2)
k_gemm_mma(const float* __restrict__ A, int lda,
           const float* __restrict__ B, int ldb,
           const float* __restrict__ bias,
           float* __restrict__ Co, int ldc,
           const float* __restrict__ res, int ldr,
           int M, int K,
           const float* __restrict__ lng, const float* __restrict__ lnb,
           float* __restrict__ xn_out) {
    extern __shared__ uint32_t smu[];
    uint32_t (*Ab0)[ALD] = (uint32_t(*)[ALD])smu;
    uint32_t (*Ab1)[ALD] = (uint32_t(*)[ALD])(smu + AOFF);
    uint32_t (*Bb0)[BLD] = (uint32_t(*)[BLD])(smu + 2*AOFF);
    uint32_t (*Bb1)[BLD] = (uint32_t(*)[BLD])(smu + 2*AOFF + BOFF);
    float    (*st)[132]  = (float(*)[132])smu;     // MODE 2 staging overlay

    const int m0 = blockIdx.y * 128, n0 = blockIdx.x * 128;
    const int tid = threadIdx.x;
    const int warp = tid >> 5, lane = tid & 31;
    const int wm = warp >> 1, wn = warp & 1;
    const int Mb = wm * 32, Nb = wn * 64;
    const int lg = lane >> 2, lt = lane & 3;
    const int lr = tid >> 1, lc = (tid & 1) * 16;
    const int kb = tid >> 3, cb = (tid & 7) * 16;

    const uint32_t aD[2] = { (uint32_t)__cvta_generic_to_shared(&Ab0[lr][lc]),
                             (uint32_t)__cvta_generic_to_shared(&Ab1[lr][lc]) };
    const uint32_t bD[2] = { (uint32_t)__cvta_generic_to_shared(&Bb0[kb][cb]),
                             (uint32_t)__cvta_generic_to_shared(&Bb1[kb][cb]) };
    const bool aIn = (m0 + lr) < M;

    auto issue = [&](int c, int buf) {
        int k0 = c * 32;
        if (aIn) {
            const float* ap = A + (size_t)(m0 + lr)*lda + k0 + lc;
#pragma unroll
            for (int i = 0; i < 4; i++) cp16(aD[buf] + i*16, ap + i*4);
        } else {
            uint32_t (*Ax)[ALD] = buf ? Ab1 : Ab0;
#pragma unroll
            for (int i = 0; i < 4; i++)
                *(float4*)&Ax[lr][lc + i*4] = make_float4(0,0,0,0);
        }
        const float* bp = B + (size_t)(k0 + kb)*ldb + n0 + cb;
#pragma unroll
        for (int i = 0; i < 4; i++) cp16(bD[buf] + i*16, bp + i*4);
        cp_commit();
    };

    float acc[2][8][4] = {};
    const int NC = K >> 5;
    issue(0, 0);
    for (int c = 0; c < NC; c++) {
        int cur = c & 1;
        if (c + 1 < NC) { issue(c+1, cur ^ 1); cp_wait<1>(); }
        else cp_wait<0>();
        __syncthreads();
        uint32_t (*Ac)[ALD] = cur ? Ab1 : Ab0;
        uint32_t (*Bc)[BLD] = cur ? Bb1 : Bb0;
#pragma unroll
        for (int kq = 0; kq < 4; kq++) {
            const int kc = kq * 8;
            uint32_t b0[8], b1[8];
#pragma unroll
            for (int nt = 0; nt < 8; nt++) {
                int colB = Nb + nt*8 + lg;
                b0[nt] = Bc[kc + lt][colB];
                b1[nt] = Bc[kc + 4 + lt][colB];
            }
#pragma unroll
            for (int mt = 0; mt < 2; mt++) {
                int rb = Mb + mt*16;
                uint32_t a0 = Ac[rb + lg    ][kc + lt];
                uint32_t a1 = Ac[rb + 8 + lg][kc + lt];
                uint32_t a2 = Ac[rb + lg    ][kc + 4 + lt];
                uint32_t a3 = Ac[rb + 8 + lg][kc + 4 + lt];
#pragma unroll
                for (int nt = 0; nt < 8; nt++)
                    mma_tf32(acc[mt][nt], a0, a1, a2, a3, b0[nt], b1[nt]);
            }
        }
        __syncthreads();
    }

    if (MODE != 2) {
#pragma unroll
        for (int mt = 0; mt < 2; mt++) {
            int r0 = m0 + Mb + mt*16 + lg;
#pragma unroll
            for (int nt = 0; nt < 8; nt++) {
                int cg = n0 + Nb + nt*8 + 2*lt;
                float2 bb = *(const float2*)(bias + cg);
#pragma unroll
                for (int hrow = 0; hrow < 2; hrow++) {
                    int m = r0 + hrow*8;
                    if (m >= M) continue;
                    float cx = acc[mt][nt][hrow*2 + 0] + bb.x;
                    float cy = acc[mt][nt][hrow*2 + 1] + bb.y;
                    if (MODE == 1) { cx = gelu_erf(cx); cy = gelu_erf(cy); }
                    *(float2*)(Co + (size_t)m*ldc + cg) = make_float2(cx, cy);
                }
            }
        }
    } else {
        // MODE 2: bias + residual -> stage to smem, then per-row LN -> Co (x_new) and xn_out
#pragma unroll
        for (int mt = 0; mt < 2; mt++) {
            int rloc = Mb + mt*16 + lg;
#pragma unroll
            for (int nt = 0; nt < 8; nt++) {
                int cl = Nb + nt*8 + 2*lt;
                int cg = n0 + cl;
                float2 bb = *(const float2*)(bias + cg);
#pragma unroll
                for (int hrow = 0; hrow < 2; hrow++) {
                    int r = rloc + hrow*8;
                    int m = m0 + r;
                    float cx = acc[mt][nt][hrow*2 + 0] + bb.x;
                    float cy = acc[mt][nt][hrow*2 + 1] + bb.y;
                    if (m < M) {
                        float2 rr = *(const float2*)(res + (size_t)m*ldr + cg);
                        cx += rr.x; cy += rr.y;
                    }
                    *(float2*)&st[r][cl] = make_float2(cx, cy);
                }
            }
        }
        __syncthreads();
#pragma unroll
        for (int rr = 0; rr < 16; rr++) {
            int r = warp * 16 + rr;
            int m = m0 + r;
            if (m >= M) continue;
            float4 xv = *(const float4*)&st[r][lane*4];
            float mn = warp_sum(xv.x+xv.y+xv.z+xv.w) * (1.0f/128.0f);
            float4 dd = make_float4(xv.x-mn, xv.y-mn, xv.z-mn, xv.w-mn);
            float var = warp_sum(dd.x*dd.x+dd.y*dd.y+dd.z*dd.z+dd.w*dd.w) * (1.0f/128.0f);
            float inv = rsqrtf(var + 1e-5f);
            float4 gv = *(const float4*)(lng + lane*4);
            float4 bv = *(const float4*)(lnb + lane*4);
            *(float4*)(Co + (size_t)m*ldc + lane*4) = xv;
            *(float4*)(xn_out + (size_t)m*DIM + lane*4) =
                make_float4(dd.x*inv*gv.x+bv.x, dd.y*inv*gv.y+bv.y,
                            dd.z*inv*gv.z+bv.z, dd.w*inv*gv.w+bv.w);
        }
    }
}

// ---------------- fused edge-proj + attention (cp.async double-buffered) ----------------
__global__ void __launch_bounds__(256, 2)
k_eattn(const int* __restrict__ src, const int* __restrict__ dst,
        const float* __restrict__ ea, const float* __restrict__ We) {
    extern __shared__ uint32_t smu[];
    uint32_t (*Ab0)[ALD] = (uint32_t(*)[ALD])smu;
    uint32_t (*Ab1)[ALD] = (uint32_t(*)[ALD])(smu + AOFF);
    uint32_t (*Bb0)[BLD] = (uint32_t(*)[BLD])(smu + 2*AOFF);
    uint32_t (*Bb1)[BLD] = (uint32_t(*)[BLD])(smu + 2*AOFF + BOFF);
    float    (*et)[132]  = (float(*)[132])smu;     // overlay after mainloop
    __shared__ int sidx[128], didx[128];

    const int tid  = threadIdx.x;
    const int warp = tid >> 5, lane = tid & 31;
    const int e0 = blockIdx.x * 128;
    if (tid < 128) { sidx[tid] = src[e0+tid]; didx[tid] = dst[e0+tid]; }
    __syncthreads();

    const int wm = warp >> 1, wn = warp & 1;
    const int Mb = wm * 32, Nb = wn * 64;
    const int lg = lane >> 2, lt = lane & 3;
    const int lr = tid >> 1, lc = (tid & 1) * 16;
    const int kb = tid >> 3, cb = (tid & 7) * 16;

    const uint32_t aD[2] = { (uint32_t)__cvta_generic_to_shared(&Ab0[lr][lc]),
                             (uint32_t)__cvta_generic_to_shared(&Ab1[lr][lc]) };
    const uint32_t bD[2] = { (uint32_t)__cvta_generic_to_shared(&Bb0[kb][cb]),
                             (uint32_t)__cvta_generic_to_shared(&Bb1[kb][cb]) };

    auto issue = [&](int c, int buf) {
        int k0 = c * 32;
        const float* ap = ea + (size_t)(e0 + lr)*64 + k0 + lc;
#pragma unroll
        for (int i = 0; i < 4; i++) cp16(aD[buf] + i*16, ap + i*4);
        const float* bp = We + (size_t)(k0 + kb)*128 + cb;
#pragma unroll
        for (int i = 0; i < 4; i++) cp16(bD[buf] + i*16, bp + i*4);
        cp_commit();
    };

    float acc[2][8][4] = {};
    issue(0, 0);
#pragma unroll
    for (int c = 0; c < 2; c++) {
        int cur = c & 1;
        if (c == 0) { issue(1, 1); cp_wait<1>(); }
        else cp_wait<0>();
        __syncthreads();
        uint32_t (*Ac)[ALD] = cur ? Ab1 : Ab0;
        uint32_t (*Bc)[BLD] = cur ? Bb1 : Bb0;
#pragma unroll
        for (int kq = 0; kq < 4; kq++) {
            const int kc = kq * 8;
            uint32_t b0[8], b1[8];
#pragma unroll
            for (int nt = 0; nt < 8; nt++) {
                int colB = Nb + nt*8 + lg;
                b0[nt] = Bc[kc + lt][colB];
                b1[nt] = Bc[kc + 4 + lt][colB];
            }
#pragma unroll
            for (int mt = 0; mt < 2; mt++) {
                int rb = Mb + mt*16;
                uint32_t a0 = Ac[rb + lg    ][kc + lt];
                uint32_t a1 = Ac[rb + 8 + lg][kc + lt];
                uint32_t a2 = Ac[rb + lg    ][kc + 4 + lt];
                uint32_t a3 = Ac[rb + 8 + lg][kc + 4 + lt];
#pragma unroll
                for (int nt = 0; nt < 8; nt++)
                    mma_tf32(acc[mt][nt], a0, a1, a2, a3, b0[nt], b1[nt]);
            }
        }
        __syncthreads();
    }

    // write e-tile to smem overlay
#pragma unroll
    for (int mt = 0; mt < 2; mt++) {
        int r0 = Mb + mt*16 + lg;
#pragma unroll
        for (int nt = 0; nt < 8; nt++) {
            int c0 = Nb + nt*8 + 2*lt;
            *(float2*)&et[r0][c0]     = make_float2(acc[mt][nt][0], acc[mt][nt][1]);
            *(float2*)&et[r0 + 8][c0] = make_float2(acc[mt][nt][2], acc[mt][nt][3]);
        }
    }
    __syncthreads();

    // attention: warp-per-edge, batched 4 edges per group for load MLP
    const int c4 = lane * 4;
#pragma unroll
    for (int grp = 0; grp < 4; grp++) {
        int base = warp * 16 + grp * 4;
        float4 q[4], k[4], v[4], ev[4];
        int dd[4];
        float pe[4];
#pragma unroll
        for (int j = 0; j < 4; j++) {
            int el = base + j;
            int s = sidx[el]; dd[j] = didx[el];
            q[j]  = *(const float4*)(g_qkvs + (size_t)dd[j]*512 + c4);
            k[j]  = *(const float4*)(g_qkvs + (size_t)s*512 + 128 + c4);
            v[j]  = *(const float4*)(g_qkvs + (size_t)s*512 + 256 + c4);
            ev[j] = *(const float4*)&et[el][c4];
        }
#pragma unroll
        for (int j = 0; j < 4; j++) {
            float part = q[j].x*(k[j].x+ev[j].x) + q[j].y*(k[j].y+ev[j].y)
                       + q[j].z*(k[j].z+ev[j].z) + q[j].w*(k[j].w+ev[j].w);
            part += __shfl_xor_sync(0xffffffffu, part, 1);
            part += __shfl_xor_sync(0xffffffffu, part, 2);
            pe[j] = expf(part * 0.25f);
        }
#pragma unroll
        for (int j = 0; j < 4; j++) {
            float m0 = pe[j]*(v[j].x+ev[j].x), m1 = pe[j]*(v[j].y+ev[j].y);
            float m2 = pe[j]*(v[j].z+ev[j].z), m3 = pe[j]*(v[j].w+ev[j].w);
            float* o = g_agg + (size_t)dd[j]*128 + c4;
            asm volatile("red.global.add.v4.f32 [%0], {%1,%2,%3,%4};"
                         :: "l"(o), "f"(m0), "f"(m1), "f"(m2), "f"(m3) : "memory");
            if ((lane & 3) == 0) {
                float* dn = g_denom + (size_t)dd[j]*NH + (lane >> 2);
                asm volatile("red.global.add.f32 [%0], %1;" :: "l"(dn), "f"(pe[j]) : "memory");
            }
        }
    }
}

// ---------------- edge update: gather-GEMM (cp.async dbl-buf) + fused gate+LN ----------------
__global__ void __launch_bounds__(256, 2)
k_edge_mma(const int* __restrict__ src, const int* __restrict__ dst,
           const float* __restrict__ ea,
           const float* __restrict__ W, const float* __restrict__ bvec,
           const float* __restrict__ eg, const float* __restrict__ ebias,
           float* __restrict__ out) {
    extern __shared__ uint32_t smu[];
    uint32_t (*Ab0)[ALD] = (uint32_t(*)[ALD])smu;
    uint32_t (*Ab1)[ALD] = (uint32_t(*)[ALD])(smu + AOFF);
    uint32_t (*Bb0)[BLD] = (uint32_t(*)[BLD])(smu + 2*AOFF);
    uint32_t (*Bb1)[BLD] = (uint32_t(*)[BLD])(smu + 2*AOFF + BOFF);
    float    (*raw)[132] = (float(*)[132])smu;
    __shared__ int sidx[128], didx[128];

    const int tid  = threadIdx.x;
    const int warp = tid >> 5, lane = tid & 31;
    const int e0 = blockIdx.x * 128;
    if (tid < 128) { sidx[tid] = src[e0+tid]; didx[tid] = dst[e0+tid]; }
    __syncthreads();

    const int wm = warp >> 1, wn = warp & 1;
    const int Mb = wm * 32, Nb = wn * 64;
    const int lg = lane >> 2, lt = lane & 3;
    const int lr = tid >> 1, lc = (tid & 1) * 16;
    const int kb = tid >> 3, cb = (tid & 7) * 16;

    const uint32_t aD[2] = { (uint32_t)__cvta_generic_to_shared(&Ab0[lr][lc]),
                             (uint32_t)__cvta_generic_to_shared(&Ab1[lr][lc]) };
    const uint32_t bD[2] = { (uint32_t)__cvta_generic_to_shared(&Bb0[kb][cb]),
                             (uint32_t)__cvta_generic_to_shared(&Bb1[kb][cb]) };

    auto issue = [&](int c, int buf) {
        int k0 = c * 32;
        const float* base; int col;
        if (k0 < 128)      { base = g_xn + (size_t)sidx[lr]*128; col = k0 + lc; }
        else if (k0 < 256) { base = g_xn + (size_t)didx[lr]*128; col = k0 - 128 + lc; }
        else               { base = ea + (size_t)(e0+lr)*64;     col = k0 - 256 + lc; }
#pragma unroll
        for (int i = 0; i < 4; i++) cp16(aD[buf] + i*16, base + col + i*4);
        const float* bp = W + (size_t)(k0 + kb)*128 + cb;
#pragma unroll
        for (int i = 0; i < 4; i++) cp16(bD[buf] + i*16, bp + i*4);
        cp_commit();
    };

    float acc[2][8][4] = {};
    issue(0, 0);
    for (int c = 0; c < 10; c++) {
        int cur = c & 1;
        if (c < 9) { issue(c+1, cur ^ 1); cp_wait<1>(); }
        else cp_wait<0>();
        __syncthreads();
        uint32_t (*Ac)[ALD] = cur ? Ab1 : Ab0;
        uint32_t (*Bc)[BLD] = cur ? Bb1 : Bb0;
#pragma unroll
        for (int kq = 0; kq < 4; kq++) {
            const int kc = kq * 8;
            uint32_t b0[8], b1[8];
#pragma unroll
            for (int nt = 0; nt < 8; nt++) {
                int colB = Nb + nt*8 + lg;
                b0[nt] = Bc[kc + lt][colB];
                b1[nt] = Bc[kc + 4 + lt][colB];
            }
#pragma unroll
            for (int mt = 0; mt < 2; mt++) {
                int rb = Mb + mt*16;
                uint32_t a0 = Ac[rb + lg    ][kc + lt];
                uint32_t a1 = Ac[rb + 8 + lg][kc + lt];
                uint32_t a2 = Ac[rb + lg    ][kc + 4 + lt];
                uint32_t a3 = Ac[rb + 8 + lg][kc + 4 + lt];
#pragma unroll
                for (int nt = 0; nt < 8; nt++)
                    mma_tf32(acc[mt][nt], a0, a1, a2, a3, b0[nt], b1[nt]);
            }
        }
        __syncthreads();
    }

    // bias + relu -> raw smem (overlays tile buffers)
#pragma unroll
    for (int mt = 0; mt < 2; mt++) {
        int r0 = Mb + mt*16 + lg;
#pragma unroll
        for (int nt = 0; nt < 8; nt++) {
            int c0 = Nb + nt*8 + 2*lt;
            float2 bb = *(const float2*)(bvec + c0);
            *(float2*)&raw[r0][c0] =
                make_float2(fmaxf(acc[mt][nt][0] + bb.x, 0.0f),
                            fmaxf(acc[mt][nt][1] + bb.y, 0.0f));
            *(float2*)&raw[r0 + 8][c0] =
                make_float2(fmaxf(acc[mt][nt][2] + bb.x, 0.0f),
                            fmaxf(acc[mt][nt][3] + bb.y, 0.0f));
        }
    }
    __syncthreads();

    // t = edge_attr + sigmoid(gate)*delta; LN over 64
#pragma unroll
    for (int half = 0; half < 2; half++) {
        int r = (tid >> 2) + half * 64;
        int q = tid & 3;
        float t[16]; float s = 0.0f;
#pragma unroll
        for (int i4 = 0; i4 < 16; i4 += 4) {
            int cc = q*16 + i4;
            float4 e4 = *(const float4*)(ea + (size_t)(e0+r)*64 + cc);
            t[i4+0] = e4.x + raw[r][cc+0] / (1.0f + expf(-raw[r][64+cc+0]));
            t[i4+1] = e4.y + raw[r][cc+1] / (1.0f + expf(-raw[r][64+cc+1]));
            t[i4+2] = e4.z + raw[r][cc+2] / (1.0f + expf(-raw[r][64+cc+2]));
            t[i4+3] = e4.w + raw[r][cc+3] / (1.0f + expf(-raw[r][64+cc+3]));
            s += t[i4+0] + t[i4+1] + t[i4+2] + t[i4+3];
        }
        s += __shfl_xor_sync(0xffffffffu, s, 1);
        s += __shfl_xor_sync(0xffffffffu, s, 2);
        float m = s * (1.0f/64.0f);
        float vs = 0.0f;
#pragma unroll
        for (int i = 0; i < 16; i++) { float dd = t[i] - m; vs += dd*dd; }
        vs += __shfl_xor_sync(0xffffffffu, vs, 1);
        vs += __shfl_xor_sync(0xffffffffu, vs, 2);
        float inv = rsqrtf(vs * (1.0f/64.0f) + 1e-5f);
#pragma unroll
        for (int i4 = 0; i4 < 16; i4 += 4) {
            int cc = q*16 + i4;
            float4 gv = *(const float4*)(eg + cc);
            float4 bb = *(const float4*)(ebias + cc);
            *(float4*)(out + (size_t)(e0+r)*64 + cc) =
                make_float4((t[i4+0]-m)*inv*gv.x+bb.x, (t[i4+1]-m)*inv*gv.y+bb.y,
                            (t[i4+2]-m)*inv*gv.z+bb.z, (t[i4+3]-m)*inv*gv.w+bb.w);
        }
    }
}

// ---------------- launcher ----------------
extern "C" void kernel_launch(void* const* d_in, const int* in_sizes, int n_in,
                              void* d_out, int out_size) {
    const float* x     = (const float*)d_in[0];
    const int*   ei    = (const int*)  d_in[1];
    const float* ea    = (const float*)d_in[2];
    const float* demb  = (const float*)d_in[3];
    const float* ng    = (const float*)d_in[4];
    const float* nbv   = (const float*)d_in[5];
    const float* Wq    = (const float*)d_in[6];
    const float* bq    = (const float*)d_in[7];
    const float* Wk    = (const float*)d_in[8];
    const float* bk    = (const float*)d_in[9];
    const float* Wv    = (const float*)d_in[10];
    const float* bv    = (const float*)d_in[11];
    const float* We    = (const float*)d_in[12];
    const float* Wskip = (const float*)d_in[13];
    const float* bskip = (const float*)d_in[14];
    const float* W1    = (const float*)d_in[15];
    const float* b1    = (const float*)d_in[16];
    const float* W2    = (const float*)d_in[17];
    const float* b2    = (const float*)d_in[18];
    const float* eung  = (const float*)d_in[19];
    const float* eunb  = (const float*)d_in[20];
    const float* euW   = (const float*)d_in[21];
    const float* eub   = (const float*)d_in[22];
    const float* eueg  = (const float*)d_in[23];
    const float* eueb  = (const float*)d_in[24];
    float* out = (float*)d_out;

    const int* src = ei;
    const int* dst = ei + EE;

    static float *p_h = nullptr, *p_qkvs = nullptr,
                 *p_h2 = nullptr, *p_ffn1 = nullptr, *p_xattn = nullptr,
                 *p_W4 = nullptr, *p_b4 = nullptr, *p_xn = nullptr;
    static bool inited = false;
    if (!inited) {
        cudaGetSymbolAddress((void**)&p_h,     g_h);
        cudaGetSymbolAddress((void**)&p_qkvs,  g_qkvs);
        cudaGetSymbolAddress((void**)&p_h2,    g_h2);
        cudaGetSymbolAddress((void**)&p_ffn1,  g_ffn1);
        cudaGetSymbolAddress((void**)&p_xattn, g_xattn);
        cudaGetSymbolAddress((void**)&p_W4,    g_W4);
        cudaGetSymbolAddress((void**)&p_b4,    g_b4);
        cudaGetSymbolAddress((void**)&p_xn,    g_xn);
        cudaFuncSetAttribute(k_gemm_mma<0>, cudaFuncAttributeMaxDynamicSharedMemorySize, MMA_SMEM);
        cudaFuncSetAttribute(k_gemm_mma<1>, cudaFuncAttributeMaxDynamicSharedMemorySize, MMA_SMEM);
        cudaFuncSetAttribute(k_gemm_mma<2>, cudaFuncAttributeMaxDynamicSharedMemorySize, MMA_SMEM);
        cudaFuncSetAttribute(k_eattn,       cudaFuncAttributeMaxDynamicSharedMemorySize, MMA_SMEM);
        cudaFuncSetAttribute(k_edge_mma,    cudaFuncAttributeMaxDynamicSharedMemorySize, MMA_SMEM);
        inited = true;
    }

    const int MB = (NN + 127) / 128;   // 391

    k_setup<<<2048, 256>>>(Wq, Wk, Wv, Wskip, bq, bk, bv, bskip);
    k_deg<<<(EE + 255)/256, 256>>>(src);
    k_node_prep<<<(NN + 7)/8, 256>>>(x, demb, ng, nbv);

    // fused QKV+skip: [50000x128] @ [128x512]  (tf32 mma)
    k_gemm_mma<0><<<dim3(4, MB), 256, MMA_SMEM>>>(p_h, 128, p_W4, 512, p_b4, p_qkvs, 512,
                                                  nullptr, 0, NN, 128, nullptr, nullptr, nullptr);

    // fused edge-proj + attention (single pass; unnormalized agg + denom)
    k_eattn<<<EE/128, 256, MMA_SMEM>>>(src, dst, ea, We);

    k_node_post<<<(NN + 7)/8, 256>>>(ng, nbv);

    // FFN (tf32 mma); FFN2 fuses the eu-LN producing g_xn
    k_gemm_mma<1><<<dim3(4, MB), 256, MMA_SMEM>>>(p_h2, 128, W1, 512, b1, p_ffn1, 512,
                                                  nullptr, 0, NN, 128, nullptr, nullptr, nullptr);
    k_gemm_mma<2><<<dim3(1, MB), 256, MMA_SMEM>>>(p_ffn1, 512, W2, 128, b2, out, 128,
                                                  p_xattn, 128, NN, 512, eung, eunb, p_xn);

    k_edge_mma<<<EE/128, 256, MMA_SMEM>>>(src, dst, ea, euW, eub, eueg, eueb,
                                          out + (size_t)NN*DIM);
}

// round 14
// speedup vs baseline: 1.1708x; 1.0000x over previous
#include <cuda_runtime.h>
#include <math.h>
#include <stdint.h>

// ---------------- problem constants ----------------
constexpr int NN   = 50000;
constexpr int EE   = 800000;
constexpr int DIM  = 128;
constexpr int NH   = 8;
constexpr int HID  = 512;

// ---------------- scratch ----------------
__device__ float g_xin  [(size_t)NN*DIM];
__device__ float g_h    [(size_t)NN*DIM];
__device__ float g_qkvs [(size_t)NN*4*DIM];   // q[0:128) k[128:256) v[256:384) skip[384:512)
__device__ float g_denom[(size_t)NN*NH];
__device__ float g_agg  [(size_t)NN*DIM];     // UNNORMALIZED sum of pe*(v+e)
__device__ float g_xattn[(size_t)NN*DIM];
__device__ float g_h2   [(size_t)NN*DIM];
__device__ float g_ffn1 [(size_t)NN*HID];
__device__ float g_xn   [(size_t)NN*DIM];
__device__ float g_W4   [(size_t)DIM*512];
__device__ float g_b4   [512];
__device__ int   g_deg  [NN];

// ---------------- helpers ----------------
__device__ __forceinline__ float warp_sum(float v) {
#pragma unroll
    for (int o = 16; o > 0; o >>= 1) v += __shfl_xor_sync(0xffffffffu, v, o);
    return v;
}
__device__ __forceinline__ void mma_tf32(float* c,
                                         uint32_t a0, uint32_t a1, uint32_t a2, uint32_t a3,
                                         uint32_t b0, uint32_t b1) {
    asm volatile("mma.sync.aligned.m16n8k8.row.col.f32.tf32.tf32.f32 "
                 "{%0,%1,%2,%3}, {%4,%5,%6,%7}, {%8,%9}, {%0,%1,%2,%3};"
                 : "+f"(c[0]), "+f"(c[1]), "+f"(c[2]), "+f"(c[3])
                 : "r"(a0), "r"(a1), "r"(a2), "r"(a3), "r"(b0), "r"(b1));
}
__device__ __forceinline__ float gelu_erf(float v) {
    return 0.5f * v * (1.0f + erff(v * 0.70710678118654752f));
}
__device__ __forceinline__ void cp16(uint32_t d, const float* g) {
    asm volatile("cp.async.cg.shared.global [%0], [%1], 16;" :: "r"(d), "l"(g) : "memory");
}
__device__ __forceinline__ void cp_commit() {
    asm volatile("cp.async.commit_group;" ::: "memory");
}
template<int N> __device__ __forceinline__ void cp_wait() {
    asm volatile("cp.async.wait_group %0;" :: "n"(N) : "memory");
}

// smem tile geometry (shared by all mma kernels)
constexpr int ALD = 36;    // A smem ld (mod 32 = 4 -> conflict-free frag reads)
constexpr int BLD = 136;   // B smem ld (mod 32 = 8)
constexpr int AOFF = 128*ALD;
constexpr int BOFF = 32*BLD;
constexpr int TILE_SMEM_U32 = 2*AOFF + 2*BOFF;   // 17920 u32 = 71680 B
constexpr int MMA_SMEM = TILE_SMEM_U32 * 4;

// ---------------- setup: zero scratch + pack weights (merged, order-independent) ----------------
__global__ void k_setup(const float* __restrict__ Wq, const float* __restrict__ Wk,
                        const float* __restrict__ Wv, const float* __restrict__ Ws,
                        const float* __restrict__ bq, const float* __restrict__ bk,
                        const float* __restrict__ bv, const float* __restrict__ bs) {
    int i  = blockIdx.x * blockDim.x + threadIdx.x;
    int st = gridDim.x * blockDim.x;
    for (int j = i; j < NN*DIM; j += st) g_agg[j] = 0.0f;
    for (int j = i; j < NN*NH;  j += st) g_denom[j] = 0.0f;
    for (int j = i; j < NN;     j += st) g_deg[j] = 0;
    if (i < DIM*DIM) {
        int r = i >> 7, c = i & 127;
        g_W4[(size_t)r*512 +       c] = Wq[i];
        g_W4[(size_t)r*512 + 128 + c] = Wk[i];
        g_W4[(size_t)r*512 + 256 + c] = Wv[i];
        g_W4[(size_t)r*512 + 384 + c] = Ws[i];
    }
    if (i < 128) {
        g_b4[i] = bq[i]; g_b4[128+i] = bk[i]; g_b4[256+i] = bv[i]; g_b4[384+i] = bs[i];
    }
}
__global__ void k_deg(const int* __restrict__ src) {
    int i = blockIdx.x * blockDim.x + threadIdx.x;
    if (i < EE) atomicAdd(&g_deg[src[i]], 1);
}

// ---------------- fused LN kernels ----------------
__global__ void k_node_prep(const float* __restrict__ x, const float* __restrict__ demb,
                            const float* __restrict__ g, const float* __restrict__ b) {
    int row = blockIdx.x * 8 + (threadIdx.x >> 5);
    if (row >= NN) return;
    int lane = threadIdx.x & 31;
    int d = g_deg[row]; if (d > 255) d = 255;
    float4 xv = *(const float4*)(x + (size_t)row*DIM + lane*4);
    float4 dv = *(const float4*)(demb + (size_t)d*DIM + lane*4);
    float4 xi = make_float4(xv.x+dv.x, xv.y+dv.y, xv.z+dv.z, xv.w+dv.w);
    *(float4*)(g_xin + (size_t)row*DIM + lane*4) = xi;
    float m = warp_sum(xi.x+xi.y+xi.z+xi.w) * (1.0f/128.0f);
    float4 dd = make_float4(xi.x-m, xi.y-m, xi.z-m, xi.w-m);
    float var = warp_sum(dd.x*dd.x+dd.y*dd.y+dd.z*dd.z+dd.w*dd.w) * (1.0f/128.0f);
    float inv = rsqrtf(var + 1e-5f);
    float4 gv = *(const float4*)(g + lane*4);
    float4 bv = *(const float4*)(b + lane*4);
    *(float4*)(g_h + (size_t)row*DIM + lane*4) =
        make_float4(dd.x*inv*gv.x+bv.x, dd.y*inv*gv.y+bv.y, dd.z*inv*gv.z+bv.z, dd.w*inv*gv.w+bv.w);
}

// x_attn = x_in + agg/denom + skip; h2 = LN(x_attn)
__global__ void k_node_post(const float* __restrict__ g, const float* __restrict__ b) {
    int row = blockIdx.x * 8 + (threadIdx.x >> 5);
    if (row >= NN) return;
    int lane = threadIdx.x & 31;
    float dn = g_denom[(size_t)row*NH + (lane >> 2)];
    float rd = (dn != 0.0f) ? (1.0f / dn) : 0.0f;
    float4 xi = *(const float4*)(g_xin + (size_t)row*DIM + lane*4);
    float4 ag = *(const float4*)(g_agg + (size_t)row*DIM + lane*4);
    float4 sk = *(const float4*)(g_qkvs + (size_t)row*512 + 384 + lane*4);
    float4 xa = make_float4(xi.x+ag.x*rd+sk.x, xi.y+ag.y*rd+sk.y,
                            xi.z+ag.z*rd+sk.z, xi.w+ag.w*rd+sk.w);
    *(float4*)(g_xattn + (size_t)row*DIM + lane*4) = xa;
    float m = warp_sum(xa.x+xa.y+xa.z+xa.w) * (1.0f/128.0f);
    float4 dd = make_float4(xa.x-m, xa.y-m, xa.z-m, xa.w-m);
    float var = warp_sum(dd.x*dd.x+dd.y*dd.y+dd.z*dd.z+dd.w*dd.w) * (1.0f/128.0f);
    float inv = rsqrtf(var + 1e-5f);
    float4 gv = *(const float4*)(g + lane*4);
    float4 bv = *(const float4*)(b + lane*4);
    *(float4*)(g_h2 + (size_t)row*DIM + lane*4) =
        make_float4(dd.x*inv*gv.x+bv.x, dd.y*inv*gv.y+bv.y, dd.z*inv*gv.z+bv.z, dd.w*inv*gv.w+bv.w);
}

// ---------------- generic tf32 mma GEMM: 128x128 tile, cp.async double-buffered ----------------
// MODE 0:+bias  1:+bias,GELU  2:+bias+res + fused row-LN -> xn_out (also writes Co)
template<int MODE>
__global__ void __launch_bounds__(256, 2)
k_gemm_mma(const float* __restrict__ A, int lda,
           const float* __restrict__ B, int ldb,
           const float* __restrict__ bias,
           float* __restrict__ Co, int ldc,
           const float* __restrict__ res, int ldr,
           int M, int K,
           const float* __restrict__ lng, const float* __restrict__ lnb,
           float* __restrict__ xn_out) {
    extern __shared__ uint32_t smu[];
    uint32_t (*Ab0)[ALD] = (uint32_t(*)[ALD])smu;
    uint32_t (*Ab1)[ALD] = (uint32_t(*)[ALD])(smu + AOFF);
    uint32_t (*Bb0)[BLD] = (uint32_t(*)[BLD])(smu + 2*AOFF);
    uint32_t (*Bb1)[BLD] = (uint32_t(*)[BLD])(smu + 2*AOFF + BOFF);
    float    (*st)[132]  = (float(*)[132])smu;     // MODE 2 staging overlay

    const int m0 = blockIdx.y * 128, n0 = blockIdx.x * 128;
    const int tid = threadIdx.x;
    const int warp = tid >> 5, lane = tid & 31;
    const int wm = warp >> 1, wn = warp & 1;
    const int Mb = wm * 32, Nb = wn * 64;
    const int lg = lane >> 2, lt = lane & 3;
    const int lr = tid >> 1, lc = (tid & 1) * 16;
    const int kb = tid >> 3, cb = (tid & 7) * 16;

    const uint32_t aD[2] = { (uint32_t)__cvta_generic_to_shared(&Ab0[lr][lc]),
                             (uint32_t)__cvta_generic_to_shared(&Ab1[lr][lc]) };
    const uint32_t bD[2] = { (uint32_t)__cvta_generic_to_shared(&Bb0[kb][cb]),
                             (uint32_t)__cvta_generic_to_shared(&Bb1[kb][cb]) };
    const bool aIn = (m0 + lr) < M;

    auto issue = [&](int c, int buf) {
        int k0 = c * 32;
        if (aIn) {
            const float* ap = A + (size_t)(m0 + lr)*lda + k0 + lc;
#pragma unroll
            for (int i = 0; i < 4; i++) cp16(aD[buf] + i*16, ap + i*4);
        } else {
            uint32_t (*Ax)[ALD] = buf ? Ab1 : Ab0;
#pragma unroll
            for (int i = 0; i < 4; i++)
                *(float4*)&Ax[lr][lc + i*4] = make_float4(0,0,0,0);
        }
        const float* bp = B + (size_t)(k0 + kb)*ldb + n0 + cb;
#pragma unroll
        for (int i = 0; i < 4; i++) cp16(bD[buf] + i*16, bp + i*4);
        cp_commit();
    };

    float acc[2][8][4] = {};
    const int NC = K >> 5;
    issue(0, 0);
    for (int c = 0; c < NC; c++) {
        int cur = c & 1;
        if (c + 1 < NC) { issue(c+1, cur ^ 1); cp_wait<1>(); }
        else cp_wait<0>();
        __syncthreads();
        uint32_t (*Ac)[ALD] = cur ? Ab1 : Ab0;
        uint32_t (*Bc)[BLD] = cur ? Bb1 : Bb0;
#pragma unroll
        for (int kq = 0; kq < 4; kq++) {
            const int kc = kq * 8;
            uint32_t b0[8], b1[8];
#pragma unroll
            for (int nt = 0; nt < 8; nt++) {
                int colB = Nb + nt*8 + lg;
                b0[nt] = Bc[kc + lt][colB];
                b1[nt] = Bc[kc + 4 + lt][colB];
            }
#pragma unroll
            for (int mt = 0; mt < 2; mt++) {
                int rb = Mb + mt*16;
                uint32_t a0 = Ac[rb + lg    ][kc + lt];
                uint32_t a1 = Ac[rb + 8 + lg][kc + lt];
                uint32_t a2 = Ac[rb + lg    ][kc + 4 + lt];
                uint32_t a3 = Ac[rb + 8 + lg][kc + 4 + lt];
#pragma unroll
                for (int nt = 0; nt < 8; nt++)
                    mma_tf32(acc[mt][nt], a0, a1, a2, a3, b0[nt], b1[nt]);
            }
        }
        __syncthreads();
    }

    if (MODE != 2) {
#pragma unroll
        for (int mt = 0; mt < 2; mt++) {
            int r0 = m0 + Mb + mt*16 + lg;
#pragma unroll
            for (int nt = 0; nt < 8; nt++) {
                int cg = n0 + Nb + nt*8 + 2*lt;
                float2 bb = *(const float2*)(bias + cg);
#pragma unroll
                for (int hrow = 0; hrow < 2; hrow++) {
                    int m = r0 + hrow*8;
                    if (m >= M) continue;
                    float cx = acc[mt][nt][hrow*2 + 0] + bb.x;
                    float cy = acc[mt][nt][hrow*2 + 1] + bb.y;
                    if (MODE == 1) { cx = gelu_erf(cx); cy = gelu_erf(cy); }
                    *(float2*)(Co + (size_t)m*ldc + cg) = make_float2(cx, cy);
                }
            }
        }
    } else {
        // MODE 2: bias + residual -> stage to smem, then per-row LN -> Co (x_new) and xn_out
#pragma unroll
        for (int mt = 0; mt < 2; mt++) {
            int rloc = Mb + mt*16 + lg;
#pragma unroll
            for (int nt = 0; nt < 8; nt++) {
                int cl = Nb + nt*8 + 2*lt;
                int cg = n0 + cl;
                float2 bb = *(const float2*)(bias + cg);
#pragma unroll
                for (int hrow = 0; hrow < 2; hrow++) {
                    int r = rloc + hrow*8;
                    int m = m0 + r;
                    float cx = acc[mt][nt][hrow*2 + 0] + bb.x;
                    float cy = acc[mt][nt][hrow*2 + 1] + bb.y;
                    if (m < M) {
                        float2 rr = *(const float2*)(res + (size_t)m*ldr + cg);
                        cx += rr.x; cy += rr.y;
                    }
                    *(float2*)&st[r][cl] = make_float2(cx, cy);
                }
            }
        }
        __syncthreads();
#pragma unroll
        for (int rr = 0; rr < 16; rr++) {
            int r = warp * 16 + rr;
            int m = m0 + r;
            if (m >= M) continue;
            float4 xv = *(const float4*)&st[r][lane*4];
            float mn = warp_sum(xv.x+xv.y+xv.z+xv.w) * (1.0f/128.0f);
            float4 dd = make_float4(xv.x-mn, xv.y-mn, xv.z-mn, xv.w-mn);
            float var = warp_sum(dd.x*dd.x+dd.y*dd.y+dd.z*dd.z+dd.w*dd.w) * (1.0f/128.0f);
            float inv = rsqrtf(var + 1e-5f);
            float4 gv = *(const float4*)(lng + lane*4);
            float4 bv = *(const float4*)(lnb + lane*4);
            *(float4*)(Co + (size_t)m*ldc + lane*4) = xv;
            *(float4*)(xn_out + (size_t)m*DIM + lane*4) =
                make_float4(dd.x*inv*gv.x+bv.x, dd.y*inv*gv.y+bv.y,
                            dd.z*inv*gv.z+bv.z, dd.w*inv*gv.w+bv.w);
        }
    }
}

// ---------------- fused edge-proj + attention (cp.async double-buffered) ----------------
__global__ void __launch_bounds__(256, 2)
k_eattn(const int* __restrict__ src, const int* __restrict__ dst,
        const float* __restrict__ ea, const float* __restrict__ We) {
    extern __shared__ uint32_t smu[];
    uint32_t (*Ab0)[ALD] = (uint32_t(*)[ALD])smu;
    uint32_t (*Ab1)[ALD] = (uint32_t(*)[ALD])(smu + AOFF);
    uint32_t (*Bb0)[BLD] = (uint32_t(*)[BLD])(smu + 2*AOFF);
    uint32_t (*Bb1)[BLD] = (uint32_t(*)[BLD])(smu + 2*AOFF + BOFF);
    float    (*et)[132]  = (float(*)[132])smu;     // overlay after mainloop
    __shared__ int sidx[128], didx[128];

    const int tid  = threadIdx.x;
    const int warp = tid >> 5, lane = tid & 31;
    const int e0 = blockIdx.x * 128;
    if (tid < 128) { sidx[tid] = src[e0+tid]; didx[tid] = dst[e0+tid]; }
    __syncthreads();

    const int wm = warp >> 1, wn = warp & 1;
    const int Mb = wm * 32, Nb = wn * 64;
    const int lg = lane >> 2, lt = lane & 3;
    const int lr = tid >> 1, lc = (tid & 1) * 16;
    const int kb = tid >> 3, cb = (tid & 7) * 16;

    const uint32_t aD[2] = { (uint32_t)__cvta_generic_to_shared(&Ab0[lr][lc]),
                             (uint32_t)__cvta_generic_to_shared(&Ab1[lr][lc]) };
    const uint32_t bD[2] = { (uint32_t)__cvta_generic_to_shared(&Bb0[kb][cb]),
                             (uint32_t)__cvta_generic_to_shared(&Bb1[kb][cb]) };

    auto issue = [&](int c, int buf) {
        int k0 = c * 32;
        const float* ap = ea + (size_t)(e0 + lr)*64 + k0 + lc;
#pragma unroll
        for (int i = 0; i < 4; i++) cp16(aD[buf] + i*16, ap + i*4);
        const float* bp = We + (size_t)(k0 + kb)*128 + cb;
#pragma unroll
        for (int i = 0; i < 4; i++) cp16(bD[buf] + i*16, bp + i*4);
        cp_commit();
    };

    float acc[2][8][4] = {};
    issue(0, 0);
#pragma unroll
    for (int c = 0; c < 2; c++) {
        int cur = c & 1;
        if (c == 0) { issue(1, 1); cp_wait<1>(); }
        else cp_wait<0>();
        __syncthreads();
        uint32_t (*Ac)[ALD] = cur ? Ab1 : Ab0;
        uint32_t (*Bc)[BLD] = cur ? Bb1 : Bb0;
#pragma unroll
        for (int kq = 0; kq < 4; kq++) {
            const int kc = kq * 8;
            uint32_t b0[8], b1[8];
#pragma unroll
            for (int nt = 0; nt < 8; nt++) {
                int colB = Nb + nt*8 + lg;
                b0[nt] = Bc[kc + lt][colB];
                b1[nt] = Bc[kc + 4 + lt][colB];
            }
#pragma unroll
            for (int mt = 0; mt < 2; mt++) {
                int rb = Mb + mt*16;
                uint32_t a0 = Ac[rb + lg    ][kc + lt];
                uint32_t a1 = Ac[rb + 8 + lg][kc + lt];
                uint32_t a2 = Ac[rb + lg    ][kc + 4 + lt];
                uint32_t a3 = Ac[rb + 8 + lg][kc + 4 + lt];
#pragma unroll
                for (int nt = 0; nt < 8; nt++)
                    mma_tf32(acc[mt][nt], a0, a1, a2, a3, b0[nt], b1[nt]);
            }
        }
        __syncthreads();
    }

    // write e-tile to smem overlay
#pragma unroll
    for (int mt = 0; mt < 2; mt++) {
        int r0 = Mb + mt*16 + lg;
#pragma unroll
        for (int nt = 0; nt < 8; nt++) {
            int c0 = Nb + nt*8 + 2*lt;
            *(float2*)&et[r0][c0]     = make_float2(acc[mt][nt][0], acc[mt][nt][1]);
            *(float2*)&et[r0 + 8][c0] = make_float2(acc[mt][nt][2], acc[mt][nt][3]);
        }
    }
    __syncthreads();

    // attention: warp-per-edge, batched 4 edges per group for load MLP
    const int c4 = lane * 4;
#pragma unroll
    for (int grp = 0; grp < 4; grp++) {
        int base = warp * 16 + grp * 4;
        float4 q[4], k[4], v[4], ev[4];
        int dd[4];
        float pe[4];
#pragma unroll
        for (int j = 0; j < 4; j++) {
            int el = base + j;
            int s = sidx[el]; dd[j] = didx[el];
            q[j]  = *(const float4*)(g_qkvs + (size_t)dd[j]*512 + c4);
            k[j]  = *(const float4*)(g_qkvs + (size_t)s*512 + 128 + c4);
            v[j]  = *(const float4*)(g_qkvs + (size_t)s*512 + 256 + c4);
            ev[j] = *(const float4*)&et[el][c4];
        }
#pragma unroll
        for (int j = 0; j < 4; j++) {
            float part = q[j].x*(k[j].x+ev[j].x) + q[j].y*(k[j].y+ev[j].y)
                       + q[j].z*(k[j].z+ev[j].z) + q[j].w*(k[j].w+ev[j].w);
            part += __shfl_xor_sync(0xffffffffu, part, 1);
            part += __shfl_xor_sync(0xffffffffu, part, 2);
            pe[j] = expf(part * 0.25f);
        }
#pragma unroll
        for (int j = 0; j < 4; j++) {
            float m0 = pe[j]*(v[j].x+ev[j].x), m1 = pe[j]*(v[j].y+ev[j].y);
            float m2 = pe[j]*(v[j].z+ev[j].z), m3 = pe[j]*(v[j].w+ev[j].w);
            float* o = g_agg + (size_t)dd[j]*128 + c4;
            asm volatile("red.global.add.v4.f32 [%0], {%1,%2,%3,%4};"
                         :: "l"(o), "f"(m0), "f"(m1), "f"(m2), "f"(m3) : "memory");
            if ((lane & 3) == 0) {
                float* dn = g_denom + (size_t)dd[j]*NH + (lane >> 2);
                asm volatile("red.global.add.f32 [%0], %1;" :: "l"(dn), "f"(pe[j]) : "memory");
            }
        }
    }
}

// ---------------- edge update: gather-GEMM (cp.async dbl-buf) + fused gate+LN ----------------
__global__ void __launch_bounds__(256, 2)
k_edge_mma(const int* __restrict__ src, const int* __restrict__ dst,
           const float* __restrict__ ea,
           const float* __restrict__ W, const float* __restrict__ bvec,
           const float* __restrict__ eg, const float* __restrict__ ebias,
           float* __restrict__ out) {
    extern __shared__ uint32_t smu[];
    uint32_t (*Ab0)[ALD] = (uint32_t(*)[ALD])smu;
    uint32_t (*Ab1)[ALD] = (uint32_t(*)[ALD])(smu + AOFF);
    uint32_t (*Bb0)[BLD] = (uint32_t(*)[BLD])(smu + 2*AOFF);
    uint32_t (*Bb1)[BLD] = (uint32_t(*)[BLD])(smu + 2*AOFF + BOFF);
    float    (*raw)[132] = (float(*)[132])smu;
    __shared__ int sidx[128], didx[128];

    const int tid  = threadIdx.x;
    const int warp = tid >> 5, lane = tid & 31;
    const int e0 = blockIdx.x * 128;
    if (tid < 128) { sidx[tid] = src[e0+tid]; didx[tid] = dst[e0+tid]; }
    __syncthreads();

    const int wm = warp >> 1, wn = warp & 1;
    const int Mb = wm * 32, Nb = wn * 64;
    const int lg = lane >> 2, lt = lane & 3;
    const int lr = tid >> 1, lc = (tid & 1) * 16;
    const int kb = tid >> 3, cb = (tid & 7) * 16;

    const uint32_t aD[2] = { (uint32_t)__cvta_generic_to_shared(&Ab0[lr][lc]),
                             (uint32_t)__cvta_generic_to_shared(&Ab1[lr][lc]) };
    const uint32_t bD[2] = { (uint32_t)__cvta_generic_to_shared(&Bb0[kb][cb]),
                             (uint32_t)__cvta_generic_to_shared(&Bb1[kb][cb]) };

    auto issue = [&](int c, int buf) {
        int k0 = c * 32;
        const float* base; int col;
        if (k0 < 128)      { base = g_xn + (size_t)sidx[lr]*128; col = k0 + lc; }
        else if (k0 < 256) { base = g_xn + (size_t)didx[lr]*128; col = k0 - 128 + lc; }
        else               { base = ea + (size_t)(e0+lr)*64;     col = k0 - 256 + lc; }
#pragma unroll
        for (int i = 0; i < 4; i++) cp16(aD[buf] + i*16, base + col + i*4);
        const float* bp = W + (size_t)(k0 + kb)*128 + cb;
#pragma unroll
        for (int i = 0; i < 4; i++) cp16(bD[buf] + i*16, bp + i*4);
        cp_commit();
    };

    float acc[2][8][4] = {};
    issue(0, 0);
    for (int c = 0; c < 10; c++) {
        int cur = c & 1;
        if (c < 9) { issue(c+1, cur ^ 1); cp_wait<1>(); }
        else cp_wait<0>();
        __syncthreads();
        uint32_t (*Ac)[ALD] = cur ? Ab1 : Ab0;
        uint32_t (*Bc)[BLD] = cur ? Bb1 : Bb0;
#pragma unroll
        for (int kq = 0; kq < 4; kq++) {
            const int kc = kq * 8;
            uint32_t b0[8], b1[8];
#pragma unroll
            for (int nt = 0; nt < 8; nt++) {
                int colB = Nb + nt*8 + lg;
                b0[nt] = Bc[kc + lt][colB];
                b1[nt] = Bc[kc + 4 + lt][colB];
            }
#pragma unroll
            for (int mt = 0; mt < 2; mt++) {
                int rb = Mb + mt*16;
                uint32_t a0 = Ac[rb + lg    ][kc + lt];
                uint32_t a1 = Ac[rb + 8 + lg][kc + lt];
                uint32_t a2 = Ac[rb + lg    ][kc + 4 + lt];
                uint32_t a3 = Ac[rb + 8 + lg][kc + 4 + lt];
#pragma unroll
                for (int nt = 0; nt < 8; nt++)
                    mma_tf32(acc[mt][nt], a0, a1, a2, a3, b0[nt], b1[nt]);
            }
        }
        __syncthreads();
    }

    // bias + relu -> raw smem (overlays tile buffers)
#pragma unroll
    for (int mt = 0; mt < 2; mt++) {
        int r0 = Mb + mt*16 + lg;
#pragma unroll
        for (int nt = 0; nt < 8; nt++) {
            int c0 = Nb + nt*8 + 2*lt;
            float2 bb = *(const float2*)(bvec + c0);
            *(float2*)&raw[r0][c0] =
                make_float2(fmaxf(acc[mt][nt][0] + bb.x, 0.0f),
                            fmaxf(acc[mt][nt][1] + bb.y, 0.0f));
            *(float2*)&raw[r0 + 8][c0] =
                make_float2(fmaxf(acc[mt][nt][2] + bb.x, 0.0f),
                            fmaxf(acc[mt][nt][3] + bb.y, 0.0f));
        }
    }
    __syncthreads();

    // t = edge_attr + sigmoid(gate)*delta; LN over 64
#pragma unroll
    for (int half = 0; half < 2; half++) {
        int r = (tid >> 2) + half * 64;
        int q = tid & 3;
        float t[16]; float s = 0.0f;
#pragma unroll
        for (int i4 = 0; i4 < 16; i4 += 4) {
            int cc = q*16 + i4;
            float4 e4 = *(const float4*)(ea + (size_t)(e0+r)*64 + cc);
            t[i4+0] = e4.x + raw[r][cc+0] / (1.0f + expf(-raw[r][64+cc+0]));
            t[i4+1] = e4.y + raw[r][cc+1] / (1.0f + expf(-raw[r][64+cc+1]));
            t[i4+2] = e4.z + raw[r][cc+2] / (1.0f + expf(-raw[r][64+cc+2]));
            t[i4+3] = e4.w + raw[r][cc+3] / (1.0f + expf(-raw[r][64+cc+3]));
            s += t[i4+0] + t[i4+1] + t[i4+2] + t[i4+3];
        }
        s += __shfl_xor_sync(0xffffffffu, s, 1);
        s += __shfl_xor_sync(0xffffffffu, s, 2);
        float m = s * (1.0f/64.0f);
        float vs = 0.0f;
#pragma unroll
        for (int i = 0; i < 16; i++) { float dd = t[i] - m; vs += dd*dd; }
        vs += __shfl_xor_sync(0xffffffffu, vs, 1);
        vs += __shfl_xor_sync(0xffffffffu, vs, 2);
        float inv = rsqrtf(vs * (1.0f/64.0f) + 1e-5f);
#pragma unroll
        for (int i4 = 0; i4 < 16; i4 += 4) {
            int cc = q*16 + i4;
            float4 gv = *(const float4*)(eg + cc);
            float4 bb = *(const float4*)(ebias + cc);
            *(float4*)(out + (size_t)(e0+r)*64 + cc) =
                make_float4((t[i4+0]-m)*inv*gv.x+bb.x, (t[i4+1]-m)*inv*gv.y+bb.y,
                            (t[i4+2]-m)*inv*gv.z+bb.z, (t[i4+3]-m)*inv*gv.w+bb.w);
        }
    }
}

// ---------------- launcher ----------------
extern "C" void kernel_launch(void* const* d_in, const int* in_sizes, int n_in,
                              void* d_out, int out_size) {
    const float* x     = (const float*)d_in[0];
    const int*   ei    = (const int*)  d_in[1];
    const float* ea    = (const float*)d_in[2];
    const float* demb  = (const float*)d_in[3];
    const float* ng    = (const float*)d_in[4];
    const float* nbv   = (const float*)d_in[5];
    const float* Wq    = (const float*)d_in[6];
    const float* bq    = (const float*)d_in[7];
    const float* Wk    = (const float*)d_in[8];
    const float* bk    = (const float*)d_in[9];
    const float* Wv    = (const float*)d_in[10];
    const float* bv    = (const float*)d_in[11];
    const float* We    = (const float*)d_in[12];
    const float* Wskip = (const float*)d_in[13];
    const float* bskip = (const float*)d_in[14];
    const float* W1    = (const float*)d_in[15];
    const float* b1    = (const float*)d_in[16];
    const float* W2    = (const float*)d_in[17];
    const float* b2    = (const float*)d_in[18];
    const float* eung  = (const float*)d_in[19];
    const float* eunb  = (const float*)d_in[20];
    const float* euW   = (const float*)d_in[21];
    const float* eub   = (const float*)d_in[22];
    const float* eueg  = (const float*)d_in[23];
    const float* eueb  = (const float*)d_in[24];
    float* out = (float*)d_out;

    const int* src = ei;
    const int* dst = ei + EE;

    static float *p_h = nullptr, *p_qkvs = nullptr,
                 *p_h2 = nullptr, *p_ffn1 = nullptr, *p_xattn = nullptr,
                 *p_W4 = nullptr, *p_b4 = nullptr, *p_xn = nullptr;
    static bool inited = false;
    if (!inited) {
        cudaGetSymbolAddress((void**)&p_h,     g_h);
        cudaGetSymbolAddress((void**)&p_qkvs,  g_qkvs);
        cudaGetSymbolAddress((void**)&p_h2,    g_h2);
        cudaGetSymbolAddress((void**)&p_ffn1,  g_ffn1);
        cudaGetSymbolAddress((void**)&p_xattn, g_xattn);
        cudaGetSymbolAddress((void**)&p_W4,    g_W4);
        cudaGetSymbolAddress((void**)&p_b4,    g_b4);
        cudaGetSymbolAddress((void**)&p_xn,    g_xn);
        cudaFuncSetAttribute(k_gemm_mma<0>, cudaFuncAttributeMaxDynamicSharedMemorySize, MMA_SMEM);
        cudaFuncSetAttribute(k_gemm_mma<1>, cudaFuncAttributeMaxDynamicSharedMemorySize, MMA_SMEM);
        cudaFuncSetAttribute(k_gemm_mma<2>, cudaFuncAttributeMaxDynamicSharedMemorySize, MMA_SMEM);
        cudaFuncSetAttribute(k_eattn,       cudaFuncAttributeMaxDynamicSharedMemorySize, MMA_SMEM);
        cudaFuncSetAttribute(k_edge_mma,    cudaFuncAttributeMaxDynamicSharedMemorySize, MMA_SMEM);
        inited = true;
    }

    const int MB = (NN + 127) / 128;   // 391

    k_setup<<<2048, 256>>>(Wq, Wk, Wv, Wskip, bq, bk, bv, bskip);
    k_deg<<<(EE + 255)/256, 256>>>(src);
    k_node_prep<<<(NN + 7)/8, 256>>>(x, demb, ng, nbv);

    // fused QKV+skip: [50000x128] @ [128x512]  (tf32 mma)
    k_gemm_mma<0><<<dim3(4, MB), 256, MMA_SMEM>>>(p_h, 128, p_W4, 512, p_b4, p_qkvs, 512,
                                                  nullptr, 0, NN, 128, nullptr, nullptr, nullptr);

    // fused edge-proj + attention (single pass; unnormalized agg + denom)
    k_eattn<<<EE/128, 256, MMA_SMEM>>>(src, dst, ea, We);

    k_node_post<<<(NN + 7)/8, 256>>>(ng, nbv);

    // FFN (tf32 mma); FFN2 fuses the eu-LN producing g_xn
    k_gemm_mma<1><<<dim3(4, MB), 256, MMA_SMEM>>>(p_h2, 128, W1, 512, b1, p_ffn1, 512,
                                                  nullptr, 0, NN, 128, nullptr, nullptr, nullptr);
    k_gemm_mma<2><<<dim3(1, MB), 256, MMA_SMEM>>>(p_ffn1, 512, W2, 128, b2, out, 128,
                                                  p_xattn, 128, NN, 512, eung, eunb, p_xn);

    k_edge_mma<<<EE/128, 256, MMA_SMEM>>>(src, dst, ea, euW, eub, eueg, eueb,
                                          out + (size_t)NN*DIM);
}